// round 4
// baseline (speedup 1.0000x reference)
#include <cuda_runtime.h>

// Problem constants
#define BATCH    4096
#define SEQT     512
#define HID      50
#define NBC      32               // batch per CTA
#define NBT      4                // batch per thread
#define BGRP     8                // batch groups
#define NTHREADS 400              // 50 units x 8 groups
#define NCTAS    128
#define JP       52               // padded j extent (cols 50,51 zero)
#define HSTRIDE  36               // u64 per h row (32 used + pad; 288B, 16B-aligned)
#define HBUF     (JP * HSTRIDE)   // u64 per h buffer = 1872
#define WPM      (HID * JP)       // u64 per gate-pair weight matrix = 2600

typedef unsigned long long u64;

__device__ __forceinline__ void fma2(u64 &acc, u64 a, u64 b) {
    asm("fma.rn.f32x2 %0, %1, %2, %0;" : "+l"(acc) : "l"(a), "l"(b));
}
__device__ __forceinline__ u64 pk2(float a, float b) {
    u64 r;
    unsigned ia = __float_as_uint(a), ib = __float_as_uint(b);
    asm("mov.b64 %0, {%1, %2};" : "=l"(r) : "r"(ia), "r"(ib));
    return r;
}
__device__ __forceinline__ float lo2(u64 v) { return __uint_as_float((unsigned)v); }
__device__ __forceinline__ float hi2(u64 v) { return __uint_as_float((unsigned)(v >> 32)); }

// clamp-free: saturates correctly at +/-inf
__device__ __forceinline__ float sigmoidf_(float z) {
    float e = __expf(-z);                 // inf ok
    return __fdividef(1.0f, 1.0f + e);    // 1/inf = 0
}
__device__ __forceinline__ float tanhf_(float z) {
    float e = __expf(2.0f * z);           // 0..inf
    return 1.0f - __fdividef(2.0f, e + 1.0f);
}

// SMEM (u64): w0if w0go w1iif w1igo w1hif w1hgo [WPM each]
//             h0[2*HBUF] h1[2*HBUF]  then float fc[64]
#define SMEM_U64   (6 * WPM + 4 * HBUF)
#define SMEM_BYTES (SMEM_U64 * 8 + 64 * 4)

__global__ __launch_bounds__(NTHREADS, 1)
void lstm_fused_kernel(const float* __restrict__ x,
                       const float* __restrict__ Wih0, const float* __restrict__ Whh0,
                       const float* __restrict__ bih0, const float* __restrict__ bhh0,
                       const float* __restrict__ Wih1, const float* __restrict__ Whh1,
                       const float* __restrict__ bih1, const float* __restrict__ bhh1,
                       const float* __restrict__ fcw_g, const float* __restrict__ fcb_g,
                       float* __restrict__ out)
{
    extern __shared__ u64 smu[];
    u64* w0if  = smu;
    u64* w0go  = w0if  + WPM;
    u64* w1iif = w0go  + WPM;
    u64* w1igo = w1iif + WPM;
    u64* w1hif = w1igo + WPM;
    u64* w1hgo = w1hif + WPM;
    u64* h0s   = w1hgo + WPM;       // [2][JP][HSTRIDE]
    u64* h1s   = h0s   + 2 * HBUF;
    float* fcws = (float*)(h1s + 2 * HBUF);   // [0:50) w, [50] bias

    const int tid = threadIdx.x;

    // ---- stage weights gate-paired: (i,f) and (g,o) pairs per (u, j) ----
    for (int idx = tid; idx < WPM; idx += NTHREADS) {
        int u = idx / JP, j = idx - u * JP;
        float a0=0.f,a1=0.f,b0=0.f,b1=0.f,c0v=0.f,c1v=0.f,d0=0.f,d1=0.f,e0=0.f,e1=0.f,f0=0.f,f1=0.f;
        if (j < HID) {
            a0  = Whh0[(u)        * HID + j];  a1  = Whh0[(HID   + u) * HID + j];
            b0  = Whh0[(2*HID + u)* HID + j];  b1  = Whh0[(3*HID + u) * HID + j];
            c0v = Wih1[(u)        * HID + j];  c1v = Wih1[(HID   + u) * HID + j];
            d0  = Wih1[(2*HID + u)* HID + j];  d1  = Wih1[(3*HID + u) * HID + j];
            e0  = Whh1[(u)        * HID + j];  e1  = Whh1[(HID   + u) * HID + j];
            f0  = Whh1[(2*HID + u)* HID + j];  f1  = Whh1[(3*HID + u) * HID + j];
        }
        w0if [idx] = pk2(a0,  a1);
        w0go [idx] = pk2(b0,  b1);
        w1iif[idx] = pk2(c0v, c1v);
        w1igo[idx] = pk2(d0,  d1);
        w1hif[idx] = pk2(e0,  e1);
        w1hgo[idx] = pk2(f0,  f1);
    }
    for (int idx = tid; idx < 4 * HBUF; idx += NTHREADS)
        h0s[idx] = 0ull;
    if (tid < HID) fcws[tid] = fcw_g[tid];
    if (tid == 0)  fcws[HID] = fcb_g[0];

    // ---- per-thread setup ----
    const int bg = tid & 7;        // batch group (fast in warp)
    const int u  = tid >> 3;       // hidden unit 0..49
    const int bb = bg * NBT;       // local batch base
    const int bo = bg * 2;         // u64 slot base within h row (first pair)

    const u64 rb0if = pk2(bih0[u] + bhh0[u],               bih0[HID + u] + bhh0[HID + u]);
    const u64 rb0go = pk2(bih0[2*HID+u] + bhh0[2*HID+u],   bih0[3*HID+u] + bhh0[3*HID+u]);
    const u64 rb1if = pk2(bih1[u] + bhh1[u],               bih1[HID + u] + bhh1[HID + u]);
    const u64 rb1go = pk2(bih1[2*HID+u] + bhh1[2*HID+u],   bih1[3*HID+u] + bhh1[3*HID+u]);
    const u64 rwxif = pk2(Wih0[u],         Wih0[HID + u]);      // IN = 1
    const u64 rwxgo = pk2(Wih0[2*HID + u], Wih0[3*HID + u]);

    const u64* w0ifr  = w0if  + u * JP;
    const u64* w0gor  = w0go  + u * JP;
    const u64* w1iifr = w1iif + u * JP;
    const u64* w1igor = w1igo + u * JP;
    const u64* w1hifr = w1hif + u * JP;
    const u64* w1hgor = w1hgo + u * JP;

    float c0[NBT] = {0.f,0.f,0.f,0.f};
    float c1[NBT] = {0.f,0.f,0.f,0.f};

    const float* xp = x + (size_t)(blockIdx.x * NBC + bb) * SEQT;
    float xv[NBT], xvn[NBT];
    #pragma unroll
    for (int nb = 0; nb < NBT; nb++) xv[nb] = xp[nb * SEQT + 0];

    __syncthreads();

    int p = 0;
    for (int t = 0; t < SEQT; t++) {
        const int q = p ^ 1;
        const int tn = (t + 1 < SEQT) ? t + 1 : t;
        #pragma unroll
        for (int nb = 0; nb < NBT; nb++) xvn[nb] = xp[nb * SEQT + tn];

        // ===== layer 0 : gates = b0 + wx*x + Whh0 @ h0(t-1) =====
        u64 aIF[NBT], aGO[NBT];
        #pragma unroll
        for (int nb = 0; nb < NBT; nb++) {
            u64 xx = pk2(xv[nb], xv[nb]);
            aIF[nb] = rb0if; fma2(aIF[nb], rwxif, xx);
            aGO[nb] = rb0go; fma2(aGO[nb], rwxgo, xx);
        }
        {
            const u64* hp = h0s + p * HBUF;
            for (int j2 = 0; j2 < JP; j2 += 2) {
                ulonglong2 wif = *(const ulonglong2*)(w0ifr + j2);
                ulonglong2 wgo = *(const ulonglong2*)(w0gor + j2);
                ulonglong2 hA0 = *(const ulonglong2*)(hp + (j2+0)*HSTRIDE + bo);
                ulonglong2 hB0 = *(const ulonglong2*)(hp + (j2+0)*HSTRIDE + 16 + bo);
                ulonglong2 hA1 = *(const ulonglong2*)(hp + (j2+1)*HSTRIDE + bo);
                ulonglong2 hB1 = *(const ulonglong2*)(hp + (j2+1)*HSTRIDE + 16 + bo);
                fma2(aIF[0], wif.x, hA0.x); fma2(aIF[1], wif.x, hA0.y);
                fma2(aIF[2], wif.x, hB0.x); fma2(aIF[3], wif.x, hB0.y);
                fma2(aGO[0], wgo.x, hA0.x); fma2(aGO[1], wgo.x, hA0.y);
                fma2(aGO[2], wgo.x, hB0.x); fma2(aGO[3], wgo.x, hB0.y);
                fma2(aIF[0], wif.y, hA1.x); fma2(aIF[1], wif.y, hA1.y);
                fma2(aIF[2], wif.y, hB1.x); fma2(aIF[3], wif.y, hB1.y);
                fma2(aGO[0], wgo.y, hA1.x); fma2(aGO[1], wgo.y, hA1.y);
                fma2(aGO[2], wgo.y, hB1.x); fma2(aGO[3], wgo.y, hB1.y);
            }
        }
        {
            float hn[NBT];
            #pragma unroll
            for (int nb = 0; nb < NBT; nb++) {
                float ig = sigmoidf_(lo2(aIF[nb]));
                float fg = sigmoidf_(hi2(aIF[nb]));
                float zg = tanhf_  (lo2(aGO[nb]));
                float og = sigmoidf_(hi2(aGO[nb]));
                c0[nb] = fg * c0[nb] + ig * zg;
                hn[nb] = og * tanhf_(c0[nb]);
            }
            u64* hw = h0s + q * HBUF + u * HSTRIDE;
            *(ulonglong2*)(hw + bo)      = make_ulonglong2(pk2(hn[0],hn[0]), pk2(hn[1],hn[1]));
            *(ulonglong2*)(hw + 16 + bo) = make_ulonglong2(pk2(hn[2],hn[2]), pk2(hn[3],hn[3]));
        }
        __syncthreads();   // h0(t) visible; the only barrier per step

        // ===== layer 1 : gates = b1 + Wih1 @ h0(t) + Whh1 @ h1(t-1) =====
        #pragma unroll
        for (int nb = 0; nb < NBT; nb++) { aIF[nb] = rb1if; aGO[nb] = rb1go; }
        {
            const u64* hap = h0s + q * HBUF;   // h0(t)
            const u64* hbp = h1s + p * HBUF;   // h1(t-1)
            for (int j2 = 0; j2 < JP; j2 += 2) {
                ulonglong2 wiif = *(const ulonglong2*)(w1iifr + j2);
                ulonglong2 wigo = *(const ulonglong2*)(w1igor + j2);
                ulonglong2 whif = *(const ulonglong2*)(w1hifr + j2);
                ulonglong2 whgo = *(const ulonglong2*)(w1hgor + j2);
                ulonglong2 aA0 = *(const ulonglong2*)(hap + (j2+0)*HSTRIDE + bo);
                ulonglong2 aB0 = *(const ulonglong2*)(hap + (j2+0)*HSTRIDE + 16 + bo);
                ulonglong2 aA1 = *(const ulonglong2*)(hap + (j2+1)*HSTRIDE + bo);
                ulonglong2 aB1 = *(const ulonglong2*)(hap + (j2+1)*HSTRIDE + 16 + bo);
                ulonglong2 bA0 = *(const ulonglong2*)(hbp + (j2+0)*HSTRIDE + bo);
                ulonglong2 bB0 = *(const ulonglong2*)(hbp + (j2+0)*HSTRIDE + 16 + bo);
                ulonglong2 bA1 = *(const ulonglong2*)(hbp + (j2+1)*HSTRIDE + bo);
                ulonglong2 bB1 = *(const ulonglong2*)(hbp + (j2+1)*HSTRIDE + 16 + bo);

                fma2(aIF[0], wiif.x, aA0.x); fma2(aIF[1], wiif.x, aA0.y);
                fma2(aIF[2], wiif.x, aB0.x); fma2(aIF[3], wiif.x, aB0.y);
                fma2(aGO[0], wigo.x, aA0.x); fma2(aGO[1], wigo.x, aA0.y);
                fma2(aGO[2], wigo.x, aB0.x); fma2(aGO[3], wigo.x, aB0.y);
                fma2(aIF[0], whif.x, bA0.x); fma2(aIF[1], whif.x, bA0.y);
                fma2(aIF[2], whif.x, bB0.x); fma2(aIF[3], whif.x, bB0.y);
                fma2(aGO[0], whgo.x, bA0.x); fma2(aGO[1], whgo.x, bA0.y);
                fma2(aGO[2], whgo.x, bB0.x); fma2(aGO[3], whgo.x, bB0.y);

                fma2(aIF[0], wiif.y, aA1.x); fma2(aIF[1], wiif.y, aA1.y);
                fma2(aIF[2], wiif.y, aB1.x); fma2(aIF[3], wiif.y, aB1.y);
                fma2(aGO[0], wigo.y, aA1.x); fma2(aGO[1], wigo.y, aA1.y);
                fma2(aGO[2], wigo.y, aB1.x); fma2(aGO[3], wigo.y, aB1.y);
                fma2(aIF[0], whif.y, bA1.x); fma2(aIF[1], whif.y, bA1.y);
                fma2(aIF[2], whif.y, bB1.x); fma2(aIF[3], whif.y, bB1.y);
                fma2(aGO[0], whgo.y, bA1.x); fma2(aGO[1], whgo.y, bA1.y);
                fma2(aGO[2], whgo.y, bB1.x); fma2(aGO[3], whgo.y, bB1.y);
            }
        }
        {
            float hn[NBT];
            #pragma unroll
            for (int nb = 0; nb < NBT; nb++) {
                float ig = sigmoidf_(lo2(aIF[nb]));
                float fg = sigmoidf_(hi2(aIF[nb]));
                float zg = tanhf_  (lo2(aGO[nb]));
                float og = sigmoidf_(hi2(aGO[nb]));
                c1[nb] = fg * c1[nb] + ig * zg;
                hn[nb] = og * tanhf_(c1[nb]);
            }
            u64* hw = h1s + q * HBUF + u * HSTRIDE;
            *(ulonglong2*)(hw + bo)      = make_ulonglong2(pk2(hn[0],hn[0]), pk2(hn[1],hn[1]));
            *(ulonglong2*)(hw + 16 + bo) = make_ulonglong2(pk2(hn[2],hn[2]), pk2(hn[3],hn[3]));
        }
        // no second barrier: next step's barrier provides the ordering
        #pragma unroll
        for (int nb = 0; nb < NBT; nb++) xv[nb] = xvn[nb];
        p = q;
    }

    __syncthreads();   // final h1 writes visible

    // ===== final projection: out[b] = h1_last[:, b] . fcw + fcb =====
    // p toggles each step; t=511 wrote buffer 0.
    if (tid < NBC) {
        const int bgf = tid >> 2, kf = tid & 3;
        const int slot = (kf >> 1) * 16 + bgf * 2 + (kf & 1);
        float acc = fcws[HID];
        #pragma unroll 10
        for (int uu = 0; uu < HID; uu++)
            acc += ((const float*)(h1s + uu * HSTRIDE + slot))[0] * fcws[uu];
        out[blockIdx.x * NBC + tid] = acc;
    }
}

extern "C" void kernel_launch(void* const* d_in, const int* in_sizes, int n_in,
                              void* d_out, int out_size)
{
    const float* x    = (const float*)d_in[0];
    const float* Wih0 = (const float*)d_in[1];
    const float* Whh0 = (const float*)d_in[2];
    const float* bih0 = (const float*)d_in[3];
    const float* bhh0 = (const float*)d_in[4];
    const float* Wih1 = (const float*)d_in[5];
    const float* Whh1 = (const float*)d_in[6];
    const float* bih1 = (const float*)d_in[7];
    const float* bhh1 = (const float*)d_in[8];
    const float* fcw  = (const float*)d_in[9];
    const float* fcb  = (const float*)d_in[10];
    float* out = (float*)d_out;

    cudaFuncSetAttribute(lstm_fused_kernel,
                         cudaFuncAttributeMaxDynamicSharedMemorySize, SMEM_BYTES);
    lstm_fused_kernel<<<NCTAS, NTHREADS, SMEM_BYTES>>>(
        x, Wih0, Whh0, bih0, bhh0, Wih1, Whh1, bih1, bhh1, fcw, fcb, out);
}

// round 6
// speedup vs baseline: 1.5004x; 1.5004x over previous
#include <cuda_runtime.h>

// Problem constants
#define BATCH    4096
#define SEQT     512
#define HID      50
#define NBC      32               // batch per CTA
#define NBT      4                // batch per thread
#define NTHREADS 832              // groupA: 0-399 (L0), pad, groupB: 416-815 (L1), pad
#define NCTAS    128
#define JP       52               // padded j extent (cols 50,51 zero)
#define HBS      (JP * NBC)       // floats per h buffer = 1664
#define WMAT     (4 * HID * JP)   // floats per weight matrix = 10400

typedef unsigned long long u64;

__device__ __forceinline__ void fma2(u64 &acc, u64 a, u64 b) {
    asm("fma.rn.f32x2 %0, %1, %2, %0;" : "+l"(acc) : "l"(a), "l"(b));
}
__device__ __forceinline__ u64 pk2(float a, float b) {
    u64 r;
    unsigned ia = __float_as_uint(a), ib = __float_as_uint(b);
    asm("mov.b64 %0, {%1, %2};" : "=l"(r) : "r"(ia), "r"(ib));
    return r;
}
__device__ __forceinline__ float lo2(u64 v) { return __uint_as_float((unsigned)v); }
__device__ __forceinline__ float hi2(u64 v) { return __uint_as_float((unsigned)(v >> 32)); }

// clamp-free: saturate correctly at +/-inf
__device__ __forceinline__ float sigmoidf_(float z) {
    float e = __expf(-z);
    return __fdividef(1.0f, 1.0f + e);
}
__device__ __forceinline__ float tanhf_(float z) {
    float e = __expf(2.0f * z);
    return 1.0f - __fdividef(2.0f, e + 1.0f);
}

// SMEM (floats):
//  w0s[WMAT] w1is[WMAT] w1hs[WMAT]              (scalar, row=(g*HID+u), JP cols)
//  h0s[2*HBS] h1s[2*HBS]                        ([JP][NBC] batch-major, buffer=t&1)
//  sb0[4*HID u64] sb1[4*HID u64] swx[4*HID u64] (duplicated-pair biases / x-weights)
//  fcw[52]
#define SB_F   (4 * HID * 2)      // 400 floats per u64 bias array
#define SMEM_FLOATS (3 * WMAT + 4 * HBS + 3 * SB_F + 52)
#define SMEM_BYTES  (SMEM_FLOATS * 4)

__global__ __launch_bounds__(NTHREADS, 1)
void lstm_fused_kernel(const float* __restrict__ x,
                       const float* __restrict__ Wih0, const float* __restrict__ Whh0,
                       const float* __restrict__ bih0, const float* __restrict__ bhh0,
                       const float* __restrict__ Wih1, const float* __restrict__ Whh1,
                       const float* __restrict__ bih1, const float* __restrict__ bhh1,
                       const float* __restrict__ fcw_g, const float* __restrict__ fcb_g,
                       float* __restrict__ out)
{
    extern __shared__ float smf[];
    float* w0s  = smf;                  // layer0 Whh
    float* w1is = w0s  + WMAT;          // layer1 Wih
    float* w1hs = w1is + WMAT;          // layer1 Whh
    float* h0s  = w1hs + WMAT;          // [2][JP][NBC]
    float* h1s  = h0s  + 2 * HBS;
    u64*   sb0  = (u64*)(h1s + 2 * HBS);    // [4*HID] (b,b) pairs
    u64*   sb1  = sb0 + 4 * HID;
    u64*   swx  = sb1 + 4 * HID;
    float* fcws = (float*)(swx + 4 * HID);  // [0:50) w, [50] bias

    const int tid = threadIdx.x;

    // ---- stage weights (row-padded to JP, tail cols zeroed) ----
    for (int idx = tid; idx < WMAT; idx += NTHREADS) {
        int row = idx / JP, col = idx - row * JP;
        float a = 0.f, b = 0.f, c = 0.f;
        if (col < HID) {
            a = Whh0[row * HID + col];
            b = Wih1[row * HID + col];
            c = Whh1[row * HID + col];
        }
        w0s[idx]  = a;
        w1is[idx] = b;
        w1hs[idx] = c;
    }
    for (int idx = tid; idx < 4 * HBS; idx += NTHREADS)
        h0s[idx] = 0.0f;
    if (tid < HID) {
        int u = tid;
        #pragma unroll
        for (int g = 0; g < 4; g++) {
            float b0v = bih0[g * HID + u] + bhh0[g * HID + u];
            float b1v = bih1[g * HID + u] + bhh1[g * HID + u];
            float wxv = Wih0[g * HID + u];       // IN = 1
            sb0[g * HID + u] = pk2(b0v, b0v);
            sb1[g * HID + u] = pk2(b1v, b1v);
            swx[g * HID + u] = pk2(wxv, wxv);
        }
        fcws[u] = fcw_g[u];
    }
    if (tid == 0) fcws[HID] = fcb_g[0];

    // ---- group / lane mapping ----
    const bool isA = (tid < 400);
    const bool isB = (tid >= 416 && tid < 816);
    const int  gt  = isA ? tid : (isB ? (tid - 416) : 0);
    const int  bg  = gt & 7;          // batch group (fast in warp -> weight broadcast)
    const int  u   = gt >> 3;         // hidden unit 0..49
    const int  bb  = bg * NBT;        // local batch base (floats)

    float cst[NBT] = {0.f, 0.f, 0.f, 0.f};   // c0 for A threads, c1 for B threads

    const float* xp = x + (size_t)(blockIdx.x * NBC + bb) * SEQT;
    float xv[NBT];
    if (isA) {
        #pragma unroll
        for (int nb = 0; nb < NBT; nb++) xv[nb] = xp[nb * SEQT + 0];
    }

    __syncthreads();

    for (int s = 0; s <= SEQT; s++) {
        if (isA) {
            if (s < SEQT) {
                // ===== layer 0, t = s : gates = b0 + wx*x(t) + Whh0 @ h0(t-1) =====
                // read h0 buffer (s-1)&1 == (s+1)&1 ; write buffer s&1
                u64 accA[4], accB[4];
                {
                    u64 xxA = pk2(xv[0], xv[1]);
                    u64 xxB = pk2(xv[2], xv[3]);
                    #pragma unroll
                    for (int g = 0; g < 4; g++) {
                        u64 bv = sb0[g * HID + u];
                        u64 wx = swx[g * HID + u];
                        accA[g] = bv; fma2(accA[g], wx, xxA);
                        accB[g] = bv; fma2(accB[g], wx, xxB);
                    }
                }
                // prefetch next x
                float xvn[NBT];
                {
                    const int tn = (s + 1 < SEQT) ? s + 1 : s;
                    #pragma unroll
                    for (int nb = 0; nb < NBT; nb++) xvn[nb] = xp[nb * SEQT + tn];
                }
                {
                    const float* w0r0 = w0s + (0 * HID + u) * JP;
                    const float* w0r1 = w0s + (1 * HID + u) * JP;
                    const float* w0r2 = w0s + (2 * HID + u) * JP;
                    const float* w0r3 = w0s + (3 * HID + u) * JP;
                    const float* hp   = h0s + ((s + 1) & 1) * HBS + bb;
                    for (int j4 = 0; j4 < JP; j4 += 4) {
                        float4 wi = *(const float4*)(w0r0 + j4);
                        float4 wf = *(const float4*)(w0r1 + j4);
                        float4 wg = *(const float4*)(w0r2 + j4);
                        float4 wo = *(const float4*)(w0r3 + j4);
                        ulonglong2 h0v = *(const ulonglong2*)(hp + (j4 + 0) * NBC);
                        ulonglong2 h1v = *(const ulonglong2*)(hp + (j4 + 1) * NBC);
                        ulonglong2 h2v = *(const ulonglong2*)(hp + (j4 + 2) * NBC);
                        ulonglong2 h3v = *(const ulonglong2*)(hp + (j4 + 3) * NBC);
                        fma2(accA[0], pk2(wi.x, wi.x), h0v.x); fma2(accB[0], pk2(wi.x, wi.x), h0v.y);
                        fma2(accA[1], pk2(wf.x, wf.x), h0v.x); fma2(accB[1], pk2(wf.x, wf.x), h0v.y);
                        fma2(accA[2], pk2(wg.x, wg.x), h0v.x); fma2(accB[2], pk2(wg.x, wg.x), h0v.y);
                        fma2(accA[3], pk2(wo.x, wo.x), h0v.x); fma2(accB[3], pk2(wo.x, wo.x), h0v.y);
                        fma2(accA[0], pk2(wi.y, wi.y), h1v.x); fma2(accB[0], pk2(wi.y, wi.y), h1v.y);
                        fma2(accA[1], pk2(wf.y, wf.y), h1v.x); fma2(accB[1], pk2(wf.y, wf.y), h1v.y);
                        fma2(accA[2], pk2(wg.y, wg.y), h1v.x); fma2(accB[2], pk2(wg.y, wg.y), h1v.y);
                        fma2(accA[3], pk2(wo.y, wo.y), h1v.x); fma2(accB[3], pk2(wo.y, wo.y), h1v.y);
                        fma2(accA[0], pk2(wi.z, wi.z), h2v.x); fma2(accB[0], pk2(wi.z, wi.z), h2v.y);
                        fma2(accA[1], pk2(wf.z, wf.z), h2v.x); fma2(accB[1], pk2(wf.z, wf.z), h2v.y);
                        fma2(accA[2], pk2(wg.z, wg.z), h2v.x); fma2(accB[2], pk2(wg.z, wg.z), h2v.y);
                        fma2(accA[3], pk2(wo.z, wo.z), h2v.x); fma2(accB[3], pk2(wo.z, wo.z), h2v.y);
                        fma2(accA[0], pk2(wi.w, wi.w), h3v.x); fma2(accB[0], pk2(wi.w, wi.w), h3v.y);
                        fma2(accA[1], pk2(wf.w, wf.w), h3v.x); fma2(accB[1], pk2(wf.w, wf.w), h3v.y);
                        fma2(accA[2], pk2(wg.w, wg.w), h3v.x); fma2(accB[2], pk2(wg.w, wg.w), h3v.y);
                        fma2(accA[3], pk2(wo.w, wo.w), h3v.x); fma2(accB[3], pk2(wo.w, wo.w), h3v.y);
                    }
                }
                {
                    float gi[4] = {lo2(accA[0]), hi2(accA[0]), lo2(accB[0]), hi2(accB[0])};
                    float gf[4] = {lo2(accA[1]), hi2(accA[1]), lo2(accB[1]), hi2(accB[1])};
                    float gz[4] = {lo2(accA[2]), hi2(accA[2]), lo2(accB[2]), hi2(accB[2])};
                    float go[4] = {lo2(accA[3]), hi2(accA[3]), lo2(accB[3]), hi2(accB[3])};
                    float hn[4];
                    #pragma unroll
                    for (int nb = 0; nb < NBT; nb++) {
                        float ig = sigmoidf_(gi[nb]);
                        float fg = sigmoidf_(gf[nb]);
                        float zg = tanhf_(gz[nb]);
                        float og = sigmoidf_(go[nb]);
                        cst[nb] = fg * cst[nb] + ig * zg;
                        hn[nb] = og * tanhf_(cst[nb]);
                    }
                    *(float4*)(h0s + (s & 1) * HBS + u * NBC + bb) =
                        make_float4(hn[0], hn[1], hn[2], hn[3]);
                }
                #pragma unroll
                for (int nb = 0; nb < NBT; nb++) xv[nb] = xvn[nb];
            }
        } else if (isB) {
            if (s >= 1) {
                // ===== layer 1, t = s-1 : gates = b1 + Wih1 @ h0(t) + Whh1 @ h1(t-1) =====
                // read h0 buffer (s-1)&1 ; read h1 buffer s&1 ; write h1 buffer (s-1)&1
                u64 accA[4], accB[4];
                #pragma unroll
                for (int g = 0; g < 4; g++) {
                    u64 bv = sb1[g * HID + u];
                    accA[g] = bv; accB[g] = bv;
                }
                {
                    const float* wir0 = w1is + (0 * HID + u) * JP;
                    const float* wir1 = w1is + (1 * HID + u) * JP;
                    const float* wir2 = w1is + (2 * HID + u) * JP;
                    const float* wir3 = w1is + (3 * HID + u) * JP;
                    const float* whr0 = w1hs + (0 * HID + u) * JP;
                    const float* whr1 = w1hs + (1 * HID + u) * JP;
                    const float* whr2 = w1hs + (2 * HID + u) * JP;
                    const float* whr3 = w1hs + (3 * HID + u) * JP;
                    const float* hap  = h0s + ((s - 1) & 1) * HBS + bb;   // h0(t)
                    const float* hbp  = h1s + (s & 1) * HBS + bb;         // h1(t-1)
                    #pragma unroll 2
                    for (int j2 = 0; j2 < JP; j2 += 2) {
                        float2 ai = *(const float2*)(wir0 + j2);
                        float2 af = *(const float2*)(wir1 + j2);
                        float2 ag = *(const float2*)(wir2 + j2);
                        float2 ao = *(const float2*)(wir3 + j2);
                        float2 ri = *(const float2*)(whr0 + j2);
                        float2 rf = *(const float2*)(whr1 + j2);
                        float2 rg = *(const float2*)(whr2 + j2);
                        float2 ro = *(const float2*)(whr3 + j2);
                        ulonglong2 a0 = *(const ulonglong2*)(hap + (j2 + 0) * NBC);
                        ulonglong2 a1 = *(const ulonglong2*)(hap + (j2 + 1) * NBC);
                        ulonglong2 b0 = *(const ulonglong2*)(hbp + (j2 + 0) * NBC);
                        ulonglong2 b1 = *(const ulonglong2*)(hbp + (j2 + 1) * NBC);

                        fma2(accA[0], pk2(ai.x, ai.x), a0.x); fma2(accB[0], pk2(ai.x, ai.x), a0.y);
                        fma2(accA[1], pk2(af.x, af.x), a0.x); fma2(accB[1], pk2(af.x, af.x), a0.y);
                        fma2(accA[2], pk2(ag.x, ag.x), a0.x); fma2(accB[2], pk2(ag.x, ag.x), a0.y);
                        fma2(accA[3], pk2(ao.x, ao.x), a0.x); fma2(accB[3], pk2(ao.x, ao.x), a0.y);
                        fma2(accA[0], pk2(ri.x, ri.x), b0.x); fma2(accB[0], pk2(ri.x, ri.x), b0.y);
                        fma2(accA[1], pk2(rf.x, rf.x), b0.x); fma2(accB[1], pk2(rf.x, rf.x), b0.y);
                        fma2(accA[2], pk2(rg.x, rg.x), b0.x); fma2(accB[2], pk2(rg.x, rg.x), b0.y);
                        fma2(accA[3], pk2(ro.x, ro.x), b0.x); fma2(accB[3], pk2(ro.x, ro.x), b0.y);

                        fma2(accA[0], pk2(ai.y, ai.y), a1.x); fma2(accB[0], pk2(ai.y, ai.y), a1.y);
                        fma2(accA[1], pk2(af.y, af.y), a1.x); fma2(accB[1], pk2(af.y, af.y), a1.y);
                        fma2(accA[2], pk2(ag.y, ag.y), a1.x); fma2(accB[2], pk2(ag.y, ag.y), a1.y);
                        fma2(accA[3], pk2(ao.y, ao.y), a1.x); fma2(accB[3], pk2(ao.y, ao.y), a1.y);
                        fma2(accA[0], pk2(ri.y, ri.y), b1.x); fma2(accB[0], pk2(ri.y, ri.y), b1.y);
                        fma2(accA[1], pk2(rf.y, rf.y), b1.x); fma2(accB[1], pk2(rf.y, rf.y), b1.y);
                        fma2(accA[2], pk2(rg.y, rg.y), b1.x); fma2(accB[2], pk2(rg.y, rg.y), b1.y);
                        fma2(accA[3], pk2(ro.y, ro.y), b1.x); fma2(accB[3], pk2(ro.y, ro.y), b1.y);
                    }
                }
                {
                    float gi[4] = {lo2(accA[0]), hi2(accA[0]), lo2(accB[0]), hi2(accB[0])};
                    float gf[4] = {lo2(accA[1]), hi2(accA[1]), lo2(accB[1]), hi2(accB[1])};
                    float gz[4] = {lo2(accA[2]), hi2(accA[2]), lo2(accB[2]), hi2(accB[2])};
                    float go[4] = {lo2(accA[3]), hi2(accA[3]), lo2(accB[3]), hi2(accB[3])};
                    float hn[4];
                    #pragma unroll
                    for (int nb = 0; nb < NBT; nb++) {
                        float ig = sigmoidf_(gi[nb]);
                        float fg = sigmoidf_(gf[nb]);
                        float zg = tanhf_(gz[nb]);
                        float og = sigmoidf_(go[nb]);
                        cst[nb] = fg * cst[nb] + ig * zg;
                        hn[nb] = og * tanhf_(cst[nb]);
                    }
                    *(float4*)(h1s + ((s - 1) & 1) * HBS + u * NBC + bb) =
                        make_float4(hn[0], hn[1], hn[2], hn[3]);
                }
            }
        }
        __syncthreads();
    }

    // ===== final projection: out[b] = h1(T-1)[:, b] . fcw + fcb =====
    // t = 511 -> h1 buffer 1
    if (tid < NBC) {
        float acc = fcws[HID];
        const float* hf = h1s + HBS;
        #pragma unroll 10
        for (int uu = 0; uu < HID; uu++)
            acc += hf[uu * NBC + tid] * fcws[uu];
        out[blockIdx.x * NBC + tid] = acc;
    }
}

extern "C" void kernel_launch(void* const* d_in, const int* in_sizes, int n_in,
                              void* d_out, int out_size)
{
    const float* x    = (const float*)d_in[0];
    const float* Wih0 = (const float*)d_in[1];
    const float* Whh0 = (const float*)d_in[2];
    const float* bih0 = (const float*)d_in[3];
    const float* bhh0 = (const float*)d_in[4];
    const float* Wih1 = (const float*)d_in[5];
    const float* Whh1 = (const float*)d_in[6];
    const float* bih1 = (const float*)d_in[7];
    const float* bhh1 = (const float*)d_in[8];
    const float* fcw  = (const float*)d_in[9];
    const float* fcb  = (const float*)d_in[10];
    float* out = (float*)d_out;

    cudaFuncSetAttribute(lstm_fused_kernel,
                         cudaFuncAttributeMaxDynamicSharedMemorySize, SMEM_BYTES);
    lstm_fused_kernel<<<NCTAS, NTHREADS, SMEM_BYTES>>>(
        x, Wih0, Whh0, bih0, bhh0, Wih1, Whh1, bih1, bhh1, fcw, fcb, out);
}

// round 7
// speedup vs baseline: 1.5194x; 1.0127x over previous
#include <cuda_runtime.h>

// Problem constants
#define BATCH    4096
#define SEQT     512
#define HID      50
#define NBC      32               // batch per CTA
#define NBT      4                // batch per thread
#define NTHREADS 832              // A: 0-399 (L0 + Wih1 partial), B: 416-815 (L1 combine)
#define NCTAS    128
#define JP       52               // padded j extent (cols 50,51 zero)
#define JA       24               // A computes Wih1 partial over j < JA; B over j >= JA
#define HBS      (JP * NBC)       // floats per h buffer = 1664
#define WMAT     (4 * HID * JP)   // floats per weight matrix = 10400
#define PZ_U64   (HID * 8 * 8)    // u64 per pz buffer = 3200 (50u x 8bg x 8 accs)

typedef unsigned long long u64;

__device__ __forceinline__ void fma2(u64 &acc, u64 a, u64 b) {
    asm("fma.rn.f32x2 %0, %1, %2, %0;" : "+l"(acc) : "l"(a), "l"(b));
}
__device__ __forceinline__ u64 pk2(float a, float b) {
    u64 r;
    unsigned ia = __float_as_uint(a), ib = __float_as_uint(b);
    asm("mov.b64 %0, {%1, %2};" : "=l"(r) : "r"(ia), "r"(ib));
    return r;
}
__device__ __forceinline__ float lo2(u64 v) { return __uint_as_float((unsigned)v); }
__device__ __forceinline__ float hi2(u64 v) { return __uint_as_float((unsigned)(v >> 32)); }

__device__ __forceinline__ float sigmoidf_(float z) {
    float e = __expf(-z);
    return __fdividef(1.0f, 1.0f + e);
}
__device__ __forceinline__ float tanhf_(float z) {
    float e = __expf(2.0f * z);
    return 1.0f - __fdividef(2.0f, e + 1.0f);
}

// SMEM: pz[2][PZ_U64] (u64) | w0s w1is w1hs (floats) | h0s[3][HBS] h1s[2][HBS] |
//       sb0 sb1 swx (u64[4*HID]) | fcw[52]
#define SMEM_BYTES (2*PZ_U64*8 + 3*WMAT*4 + 5*HBS*4 + 3*4*HID*8 + 52*4)

__global__ __launch_bounds__(NTHREADS, 1)
void lstm_fused_kernel(const float* __restrict__ x,
                       const float* __restrict__ Wih0, const float* __restrict__ Whh0,
                       const float* __restrict__ bih0, const float* __restrict__ bhh0,
                       const float* __restrict__ Wih1, const float* __restrict__ Whh1,
                       const float* __restrict__ bih1, const float* __restrict__ bhh1,
                       const float* __restrict__ fcw_g, const float* __restrict__ fcb_g,
                       float* __restrict__ out)
{
    extern __shared__ u64 smu[];
    u64*   pz   = smu;                        // [2][PZ_U64]
    float* w0s  = (float*)(pz + 2 * PZ_U64);  // layer0 Whh   [4H][JP]
    float* w1is = w0s  + WMAT;                // layer1 Wih
    float* w1hs = w1is + WMAT;                // layer1 Whh
    float* h0s  = w1hs + WMAT;                // [3][JP][NBC]
    float* h1s  = h0s  + 3 * HBS;             // [2][JP][NBC]
    u64*   sb0  = (u64*)(h1s + 2 * HBS);      // [4*HID] (b,b) pairs
    u64*   sb1  = sb0 + 4 * HID;
    u64*   swx  = sb1 + 4 * HID;
    float* fcws = (float*)(swx + 4 * HID);    // [0:50) w, [50] bias

    const int tid = threadIdx.x;

    // ---- stage weights (row-padded to JP, tail cols zeroed) ----
    for (int idx = tid; idx < WMAT; idx += NTHREADS) {
        int row = idx / JP, col = idx - row * JP;
        float a = 0.f, b = 0.f, c = 0.f;
        if (col < HID) {
            a = Whh0[row * HID + col];
            b = Wih1[row * HID + col];
            c = Whh1[row * HID + col];
        }
        w0s[idx]  = a;
        w1is[idx] = b;
        w1hs[idx] = c;
    }
    for (int idx = tid; idx < 5 * HBS; idx += NTHREADS)
        h0s[idx] = 0.0f;                      // zeros h0[3] and h1[2]
    if (tid < HID) {
        int u = tid;
        #pragma unroll
        for (int g = 0; g < 4; g++) {
            float b0v = bih0[g * HID + u] + bhh0[g * HID + u];
            float b1v = bih1[g * HID + u] + bhh1[g * HID + u];
            float wxv = Wih0[g * HID + u];     // IN = 1
            sb0[g * HID + u] = pk2(b0v, b0v);
            sb1[g * HID + u] = pk2(b1v, b1v);
            swx[g * HID + u] = pk2(wxv, wxv);
        }
        fcws[u] = fcw_g[u];
    }
    if (tid == 0) fcws[HID] = fcb_g[0];

    // ---- group / lane mapping ----
    const bool isA = (tid < 400);
    const bool isB = (tid >= 416 && tid < 816);
    const int  gt  = isA ? tid : (isB ? (tid - 416) : 0);
    const int  bg  = gt & 7;
    const int  u   = gt >> 3;
    const int  bb  = bg * NBT;

    float cst[NBT] = {0.f, 0.f, 0.f, 0.f};   // c0 for A, c1 for B

    const float* xp = x + (size_t)(blockIdx.x * NBC + bb) * SEQT;
    float xv[NBT];
    if (isA) {
        #pragma unroll
        for (int nb = 0; nb < NBT; nb++) xv[nb] = xp[nb * SEQT + 0];
    }

    __syncthreads();

    for (int s = 0; s <= SEQT + 1; s++) {
        const int m_w  = s % 3;            // h0 write buffer   (h0(s))
        const int m_r1 = (s + 2) % 3;      // h0(s-1)
        const int m_r2 = (s + 1) % 3;      // h0(s-2)

        if (isA) {
            if (s < SEQT) {
                // ===== layer 0, t = s =====
                u64 accA[4], accB[4];
                {
                    u64 xxA = pk2(xv[0], xv[1]);
                    u64 xxB = pk2(xv[2], xv[3]);
                    #pragma unroll
                    for (int g = 0; g < 4; g++) {
                        u64 bv = sb0[g * HID + u];
                        u64 wx = swx[g * HID + u];
                        accA[g] = bv; fma2(accA[g], wx, xxA);
                        accB[g] = bv; fma2(accB[g], wx, xxB);
                    }
                }
                float xvn[NBT];
                {
                    const int tn = (s + 1 < SEQT) ? s + 1 : s;
                    #pragma unroll
                    for (int nb = 0; nb < NBT; nb++) xvn[nb] = xp[nb * SEQT + tn];
                }
                {
                    const float* w0r0 = w0s + (0 * HID + u) * JP;
                    const float* w0r1 = w0s + (1 * HID + u) * JP;
                    const float* w0r2 = w0s + (2 * HID + u) * JP;
                    const float* w0r3 = w0s + (3 * HID + u) * JP;
                    const float* hp   = h0s + m_r1 * HBS + bb;
                    for (int j4 = 0; j4 < JP; j4 += 4) {
                        float4 wi = *(const float4*)(w0r0 + j4);
                        float4 wf = *(const float4*)(w0r1 + j4);
                        float4 wg = *(const float4*)(w0r2 + j4);
                        float4 wo = *(const float4*)(w0r3 + j4);
                        ulonglong2 h0v = *(const ulonglong2*)(hp + (j4 + 0) * NBC);
                        ulonglong2 h1v = *(const ulonglong2*)(hp + (j4 + 1) * NBC);
                        ulonglong2 h2v = *(const ulonglong2*)(hp + (j4 + 2) * NBC);
                        ulonglong2 h3v = *(const ulonglong2*)(hp + (j4 + 3) * NBC);
                        fma2(accA[0], pk2(wi.x, wi.x), h0v.x); fma2(accB[0], pk2(wi.x, wi.x), h0v.y);
                        fma2(accA[1], pk2(wf.x, wf.x), h0v.x); fma2(accB[1], pk2(wf.x, wf.x), h0v.y);
                        fma2(accA[2], pk2(wg.x, wg.x), h0v.x); fma2(accB[2], pk2(wg.x, wg.x), h0v.y);
                        fma2(accA[3], pk2(wo.x, wo.x), h0v.x); fma2(accB[3], pk2(wo.x, wo.x), h0v.y);
                        fma2(accA[0], pk2(wi.y, wi.y), h1v.x); fma2(accB[0], pk2(wi.y, wi.y), h1v.y);
                        fma2(accA[1], pk2(wf.y, wf.y), h1v.x); fma2(accB[1], pk2(wf.y, wf.y), h1v.y);
                        fma2(accA[2], pk2(wg.y, wg.y), h1v.x); fma2(accB[2], pk2(wg.y, wg.y), h1v.y);
                        fma2(accA[3], pk2(wo.y, wo.y), h1v.x); fma2(accB[3], pk2(wo.y, wo.y), h1v.y);
                        fma2(accA[0], pk2(wi.z, wi.z), h2v.x); fma2(accB[0], pk2(wi.z, wi.z), h2v.y);
                        fma2(accA[1], pk2(wf.z, wf.z), h2v.x); fma2(accB[1], pk2(wf.z, wf.z), h2v.y);
                        fma2(accA[2], pk2(wg.z, wg.z), h2v.x); fma2(accB[2], pk2(wg.z, wg.z), h2v.y);
                        fma2(accA[3], pk2(wo.z, wo.z), h2v.x); fma2(accB[3], pk2(wo.z, wo.z), h2v.y);
                        fma2(accA[0], pk2(wi.w, wi.w), h3v.x); fma2(accB[0], pk2(wi.w, wi.w), h3v.y);
                        fma2(accA[1], pk2(wf.w, wf.w), h3v.x); fma2(accB[1], pk2(wf.w, wf.w), h3v.y);
                        fma2(accA[2], pk2(wg.w, wg.w), h3v.x); fma2(accB[2], pk2(wg.w, wg.w), h3v.y);
                        fma2(accA[3], pk2(wo.w, wo.w), h3v.x); fma2(accB[3], pk2(wo.w, wo.w), h3v.y);
                    }
                }
                {
                    float gi[4] = {lo2(accA[0]), hi2(accA[0]), lo2(accB[0]), hi2(accB[0])};
                    float gf[4] = {lo2(accA[1]), hi2(accA[1]), lo2(accB[1]), hi2(accB[1])};
                    float gz[4] = {lo2(accA[2]), hi2(accA[2]), lo2(accB[2]), hi2(accB[2])};
                    float go[4] = {lo2(accA[3]), hi2(accA[3]), lo2(accB[3]), hi2(accB[3])};
                    float hn[4];
                    #pragma unroll
                    for (int nb = 0; nb < NBT; nb++) {
                        float ig = sigmoidf_(gi[nb]);
                        float fg = sigmoidf_(gf[nb]);
                        float zg = tanhf_(gz[nb]);
                        float og = sigmoidf_(go[nb]);
                        cst[nb] = fg * cst[nb] + ig * zg;
                        hn[nb] = og * tanhf_(cst[nb]);
                    }
                    *(float4*)(h0s + m_w * HBS + u * NBC + bb) =
                        make_float4(hn[0], hn[1], hn[2], hn[3]);
                }
                #pragma unroll
                for (int nb = 0; nb < NBT; nb++) xv[nb] = xvn[nb];
            }
            if (s <= SEQT) {
                // ===== partialA(t = s-1) = b1 + Wih1[:, 0:JA] @ h0(s-1) =====
                u64 accA[4], accB[4];
                #pragma unroll
                for (int g = 0; g < 4; g++) {
                    u64 bv = sb1[g * HID + u];
                    accA[g] = bv; accB[g] = bv;
                }
                {
                    const float* wr0 = w1is + (0 * HID + u) * JP;
                    const float* wr1 = w1is + (1 * HID + u) * JP;
                    const float* wr2 = w1is + (2 * HID + u) * JP;
                    const float* wr3 = w1is + (3 * HID + u) * JP;
                    const float* hp  = h0s + m_r1 * HBS + bb;
                    for (int j4 = 0; j4 < JA; j4 += 4) {
                        float4 wi = *(const float4*)(wr0 + j4);
                        float4 wf = *(const float4*)(wr1 + j4);
                        float4 wg = *(const float4*)(wr2 + j4);
                        float4 wo = *(const float4*)(wr3 + j4);
                        ulonglong2 h0v = *(const ulonglong2*)(hp + (j4 + 0) * NBC);
                        ulonglong2 h1v = *(const ulonglong2*)(hp + (j4 + 1) * NBC);
                        ulonglong2 h2v = *(const ulonglong2*)(hp + (j4 + 2) * NBC);
                        ulonglong2 h3v = *(const ulonglong2*)(hp + (j4 + 3) * NBC);
                        fma2(accA[0], pk2(wi.x, wi.x), h0v.x); fma2(accB[0], pk2(wi.x, wi.x), h0v.y);
                        fma2(accA[1], pk2(wf.x, wf.x), h0v.x); fma2(accB[1], pk2(wf.x, wf.x), h0v.y);
                        fma2(accA[2], pk2(wg.x, wg.x), h0v.x); fma2(accB[2], pk2(wg.x, wg.x), h0v.y);
                        fma2(accA[3], pk2(wo.x, wo.x), h0v.x); fma2(accB[3], pk2(wo.x, wo.x), h0v.y);
                        fma2(accA[0], pk2(wi.y, wi.y), h1v.x); fma2(accB[0], pk2(wi.y, wi.y), h1v.y);
                        fma2(accA[1], pk2(wf.y, wf.y), h1v.x); fma2(accB[1], pk2(wf.y, wf.y), h1v.y);
                        fma2(accA[2], pk2(wg.y, wg.y), h1v.x); fma2(accB[2], pk2(wg.y, wg.y), h1v.y);
                        fma2(accA[3], pk2(wo.y, wo.y), h1v.x); fma2(accB[3], pk2(wo.y, wo.y), h1v.y);
                        fma2(accA[0], pk2(wi.z, wi.z), h2v.x); fma2(accB[0], pk2(wi.z, wi.z), h2v.y);
                        fma2(accA[1], pk2(wf.z, wf.z), h2v.x); fma2(accB[1], pk2(wf.z, wf.z), h2v.y);
                        fma2(accA[2], pk2(wg.z, wg.z), h2v.x); fma2(accB[2], pk2(wg.z, wg.z), h2v.y);
                        fma2(accA[3], pk2(wo.z, wo.z), h2v.x); fma2(accB[3], pk2(wo.z, wo.z), h2v.y);
                        fma2(accA[0], pk2(wi.w, wi.w), h3v.x); fma2(accB[0], pk2(wi.w, wi.w), h3v.y);
                        fma2(accA[1], pk2(wf.w, wf.w), h3v.x); fma2(accB[1], pk2(wf.w, wf.w), h3v.y);
                        fma2(accA[2], pk2(wg.w, wg.w), h3v.x); fma2(accB[2], pk2(wg.w, wg.w), h3v.y);
                        fma2(accA[3], pk2(wo.w, wo.w), h3v.x); fma2(accB[3], pk2(wo.w, wo.w), h3v.y);
                    }
                }
                u64* pzw = pz + (s & 1) * PZ_U64 + (u * 8 + bg) * 8;
                *(ulonglong2*)(pzw + 0) = make_ulonglong2(accA[0], accA[1]);
                *(ulonglong2*)(pzw + 2) = make_ulonglong2(accA[2], accA[3]);
                *(ulonglong2*)(pzw + 4) = make_ulonglong2(accB[0], accB[1]);
                *(ulonglong2*)(pzw + 6) = make_ulonglong2(accB[2], accB[3]);
            }
        } else if (isB) {
            if (s >= 2) {
                // ===== layer 1, t = s-2 :
                //   gates = partialA(t) + Wih1[:,JA:]@h0(t) + Whh1@h1(t-1) =====
                u64 accA[4], accB[4];
                {
                    const u64* pzr = pz + ((s + 1) & 1) * PZ_U64 + (u * 8 + bg) * 8;
                    ulonglong2 p0 = *(const ulonglong2*)(pzr + 0);
                    ulonglong2 p1 = *(const ulonglong2*)(pzr + 2);
                    ulonglong2 p2 = *(const ulonglong2*)(pzr + 4);
                    ulonglong2 p3 = *(const ulonglong2*)(pzr + 6);
                    accA[0] = p0.x; accA[1] = p0.y; accA[2] = p1.x; accA[3] = p1.y;
                    accB[0] = p2.x; accB[1] = p2.y; accB[2] = p3.x; accB[3] = p3.y;
                }
                {
                    // Whh1 @ h1(t-1), full JP
                    const float* wr0 = w1hs + (0 * HID + u) * JP;
                    const float* wr1 = w1hs + (1 * HID + u) * JP;
                    const float* wr2 = w1hs + (2 * HID + u) * JP;
                    const float* wr3 = w1hs + (3 * HID + u) * JP;
                    const float* hp  = h1s + ((s + 1) & 1) * HBS + bb;   // h1(t-1)
                    for (int j4 = 0; j4 < JP; j4 += 4) {
                        float4 wi = *(const float4*)(wr0 + j4);
                        float4 wf = *(const float4*)(wr1 + j4);
                        float4 wg = *(const float4*)(wr2 + j4);
                        float4 wo = *(const float4*)(wr3 + j4);
                        ulonglong2 h0v = *(const ulonglong2*)(hp + (j4 + 0) * NBC);
                        ulonglong2 h1v = *(const ulonglong2*)(hp + (j4 + 1) * NBC);
                        ulonglong2 h2v = *(const ulonglong2*)(hp + (j4 + 2) * NBC);
                        ulonglong2 h3v = *(const ulonglong2*)(hp + (j4 + 3) * NBC);
                        fma2(accA[0], pk2(wi.x, wi.x), h0v.x); fma2(accB[0], pk2(wi.x, wi.x), h0v.y);
                        fma2(accA[1], pk2(wf.x, wf.x), h0v.x); fma2(accB[1], pk2(wf.x, wf.x), h0v.y);
                        fma2(accA[2], pk2(wg.x, wg.x), h0v.x); fma2(accB[2], pk2(wg.x, wg.x), h0v.y);
                        fma2(accA[3], pk2(wo.x, wo.x), h0v.x); fma2(accB[3], pk2(wo.x, wo.x), h0v.y);
                        fma2(accA[0], pk2(wi.y, wi.y), h1v.x); fma2(accB[0], pk2(wi.y, wi.y), h1v.y);
                        fma2(accA[1], pk2(wf.y, wf.y), h1v.x); fma2(accB[1], pk2(wf.y, wf.y), h1v.y);
                        fma2(accA[2], pk2(wg.y, wg.y), h1v.x); fma2(accB[2], pk2(wg.y, wg.y), h1v.y);
                        fma2(accA[3], pk2(wo.y, wo.y), h1v.x); fma2(accB[3], pk2(wo.y, wo.y), h1v.y);
                        fma2(accA[0], pk2(wi.z, wi.z), h2v.x); fma2(accB[0], pk2(wi.z, wi.z), h2v.y);
                        fma2(accA[1], pk2(wf.z, wf.z), h2v.x); fma2(accB[1], pk2(wf.z, wf.z), h2v.y);
                        fma2(accA[2], pk2(wg.z, wg.z), h2v.x); fma2(accB[2], pk2(wg.z, wg.z), h2v.y);
                        fma2(accA[3], pk2(wo.z, wo.z), h2v.x); fma2(accB[3], pk2(wo.z, wo.z), h2v.y);
                        fma2(accA[0], pk2(wi.w, wi.w), h3v.x); fma2(accB[0], pk2(wi.w, wi.w), h3v.y);
                        fma2(accA[1], pk2(wf.w, wf.w), h3v.x); fma2(accB[1], pk2(wf.w, wf.w), h3v.y);
                        fma2(accA[2], pk2(wg.w, wg.w), h3v.x); fma2(accB[2], pk2(wg.w, wg.w), h3v.y);
                        fma2(accA[3], pk2(wo.w, wo.w), h3v.x); fma2(accB[3], pk2(wo.w, wo.w), h3v.y);
                    }
                }
                {
                    // Wih1[:, JA:] @ h0(t)
                    const float* wr0 = w1is + (0 * HID + u) * JP;
                    const float* wr1 = w1is + (1 * HID + u) * JP;
                    const float* wr2 = w1is + (2 * HID + u) * JP;
                    const float* wr3 = w1is + (3 * HID + u) * JP;
                    const float* hp  = h0s + m_r2 * HBS + bb;            // h0(t = s-2)
                    for (int j4 = JA; j4 < JP; j4 += 4) {
                        float4 wi = *(const float4*)(wr0 + j4);
                        float4 wf = *(const float4*)(wr1 + j4);
                        float4 wg = *(const float4*)(wr2 + j4);
                        float4 wo = *(const float4*)(wr3 + j4);
                        ulonglong2 h0v = *(const ulonglong2*)(hp + (j4 + 0) * NBC);
                        ulonglong2 h1v = *(const ulonglong2*)(hp + (j4 + 1) * NBC);
                        ulonglong2 h2v = *(const ulonglong2*)(hp + (j4 + 2) * NBC);
                        ulonglong2 h3v = *(const ulonglong2*)(hp + (j4 + 3) * NBC);
                        fma2(accA[0], pk2(wi.x, wi.x), h0v.x); fma2(accB[0], pk2(wi.x, wi.x), h0v.y);
                        fma2(accA[1], pk2(wf.x, wf.x), h0v.x); fma2(accB[1], pk2(wf.x, wf.x), h0v.y);
                        fma2(accA[2], pk2(wg.x, wg.x), h0v.x); fma2(accB[2], pk2(wg.x, wg.x), h0v.y);
                        fma2(accA[3], pk2(wo.x, wo.x), h0v.x); fma2(accB[3], pk2(wo.x, wo.x), h0v.y);
                        fma2(accA[0], pk2(wi.y, wi.y), h1v.x); fma2(accB[0], pk2(wi.y, wi.y), h1v.y);
                        fma2(accA[1], pk2(wf.y, wf.y), h1v.x); fma2(accB[1], pk2(wf.y, wf.y), h1v.y);
                        fma2(accA[2], pk2(wg.y, wg.y), h1v.x); fma2(accB[2], pk2(wg.y, wg.y), h1v.y);
                        fma2(accA[3], pk2(wo.y, wo.y), h1v.x); fma2(accB[3], pk2(wo.y, wo.y), h1v.y);
                        fma2(accA[0], pk2(wi.z, wi.z), h2v.x); fma2(accB[0], pk2(wi.z, wi.z), h2v.y);
                        fma2(accA[1], pk2(wf.z, wf.z), h2v.x); fma2(accB[1], pk2(wf.z, wf.z), h2v.y);
                        fma2(accA[2], pk2(wg.z, wg.z), h2v.x); fma2(accB[2], pk2(wg.z, wg.z), h2v.y);
                        fma2(accA[3], pk2(wo.z, wo.z), h2v.x); fma2(accB[3], pk2(wo.z, wo.z), h2v.y);
                        fma2(accA[0], pk2(wi.w, wi.w), h3v.x); fma2(accB[0], pk2(wi.w, wi.w), h3v.y);
                        fma2(accA[1], pk2(wf.w, wf.w), h3v.x); fma2(accB[1], pk2(wf.w, wf.w), h3v.y);
                        fma2(accA[2], pk2(wg.w, wg.w), h3v.x); fma2(accB[2], pk2(wg.w, wg.w), h3v.y);
                        fma2(accA[3], pk2(wo.w, wo.w), h3v.x); fma2(accB[3], pk2(wo.w, wo.w), h3v.y);
                    }
                }
                {
                    float gi[4] = {lo2(accA[0]), hi2(accA[0]), lo2(accB[0]), hi2(accB[0])};
                    float gf[4] = {lo2(accA[1]), hi2(accA[1]), lo2(accB[1]), hi2(accB[1])};
                    float gz[4] = {lo2(accA[2]), hi2(accA[2]), lo2(accB[2]), hi2(accB[2])};
                    float go[4] = {lo2(accA[3]), hi2(accA[3]), lo2(accB[3]), hi2(accB[3])};
                    float hn[4];
                    #pragma unroll
                    for (int nb = 0; nb < NBT; nb++) {
                        float ig = sigmoidf_(gi[nb]);
                        float fg = sigmoidf_(gf[nb]);
                        float zg = tanhf_(gz[nb]);
                        float og = sigmoidf_(go[nb]);
                        cst[nb] = fg * cst[nb] + ig * zg;
                        hn[nb] = og * tanhf_(cst[nb]);
                    }
                    *(float4*)(h1s + (s & 1) * HBS + u * NBC + bb) =
                        make_float4(hn[0], hn[1], hn[2], hn[3]);
                }
            }
        }
        __syncthreads();
    }

    // ===== final projection: out[b] = h1(T-1)[:, b] . fcw + fcb =====
    // h1(511) written at s=513 into parity (513&1)=1 -> buffer 1
    if (tid < NBC) {
        float acc = fcws[HID];
        const float* hf = h1s + HBS;
        #pragma unroll 10
        for (int uu = 0; uu < HID; uu++)
            acc += hf[uu * NBC + tid] * fcws[uu];
        out[blockIdx.x * NBC + tid] = acc;
    }
}

extern "C" void kernel_launch(void* const* d_in, const int* in_sizes, int n_in,
                              void* d_out, int out_size)
{
    const float* x    = (const float*)d_in[0];
    const float* Wih0 = (const float*)d_in[1];
    const float* Whh0 = (const float*)d_in[2];
    const float* bih0 = (const float*)d_in[3];
    const float* bhh0 = (const float*)d_in[4];
    const float* Wih1 = (const float*)d_in[5];
    const float* Whh1 = (const float*)d_in[6];
    const float* bih1 = (const float*)d_in[7];
    const float* bhh1 = (const float*)d_in[8];
    const float* fcw  = (const float*)d_in[9];
    const float* fcb  = (const float*)d_in[10];
    float* out = (float*)d_out;

    cudaFuncSetAttribute(lstm_fused_kernel,
                         cudaFuncAttributeMaxDynamicSharedMemorySize, SMEM_BYTES);
    lstm_fused_kernel<<<NCTAS, NTHREADS, SMEM_BYTES>>>(
        x, Wih0, Whh0, bih0, bhh0, Wih1, Whh1, bih1, bhh1, fcw, fcb, out);
}

// round 13
// speedup vs baseline: 1.5427x; 1.0153x over previous
#include <cuda_runtime.h>

// Problem constants
#define BATCH    4096
#define SEQT     512
#define HID      50
#define NBC      32               // batch per CTA
#define NBT      4                // batch per thread
#define NTHREADS 832              // A: 0-399 (L0 + Wih1 partial), B: 416-815 (L1 combine)
#define NCTAS    128
#define JP       52               // padded j extent (cols 50,51 zero)
#define JA       24               // A computes Wih1 partial over j < JA; B over j >= JA
#define HBS      (JP * NBC)       // floats per h buffer = 1664
#define WMAT     (4 * HID * JP)   // floats per weight matrix = 10400
#define PZ_U64   (HID * 8 * 8)    // u64 per pz buffer = 3200

typedef unsigned long long u64;

__device__ __forceinline__ void fma2(u64 &acc, u64 a, u64 b) {
    asm("fma.rn.f32x2 %0, %1, %2, %0;" : "+l"(acc) : "l"(a), "l"(b));
}
__device__ __forceinline__ u64 pk2(float a, float b) {
    u64 r;
    unsigned ia = __float_as_uint(a), ib = __float_as_uint(b);
    asm("mov.b64 %0, {%1, %2};" : "=l"(r) : "r"(ia), "r"(ib));
    return r;
}
__device__ __forceinline__ float lo2(u64 v) { return __uint_as_float((unsigned)v); }
__device__ __forceinline__ float hi2(u64 v) { return __uint_as_float((unsigned)(v >> 32)); }

// HW tanh (MUFU, sm_75+)
__device__ __forceinline__ float tanha(float z) {
    float r;
    asm("tanh.approx.f32 %0, %1;" : "=f"(r) : "f"(z));
    return r;
}
// sigmoid with pre-halved argument: sig(2z') = 0.5 + 0.5*tanh(z')
__device__ __forceinline__ float sig_h(float zh) {
    return fmaf(0.5f, tanha(zh), 0.5f);
}

// SMEM: pz[2][PZ_U64] (u64) | w0s w1is w1hs (floats) | h0s[3][HBS] h1s[2][HBS] |
//       sb0 sb1 swx (u64[4*HID]) | fcw[52]
#define SMEM_BYTES (2*PZ_U64*8 + 3*WMAT*4 + 5*HBS*4 + 3*4*HID*8 + 52*4)

__global__ __launch_bounds__(NTHREADS, 1)
void lstm_fused_kernel(const float* __restrict__ x,
                       const float* __restrict__ Wih0, const float* __restrict__ Whh0,
                       const float* __restrict__ bih0, const float* __restrict__ bhh0,
                       const float* __restrict__ Wih1, const float* __restrict__ Whh1,
                       const float* __restrict__ bih1, const float* __restrict__ bhh1,
                       const float* __restrict__ fcw_g, const float* __restrict__ fcb_g,
                       float* __restrict__ out)
{
    extern __shared__ u64 smu[];
    u64*   pz   = smu;                        // [2][PZ_U64]
    float* w0s  = (float*)(pz + 2 * PZ_U64);  // layer0 Whh   [4H][JP]
    float* w1is = w0s  + WMAT;                // layer1 Wih
    float* w1hs = w1is + WMAT;                // layer1 Whh
    float* h0s  = w1hs + WMAT;                // [3][JP][NBC]
    float* h1s  = h0s  + 3 * HBS;             // [2][JP][NBC]
    u64*   sb0  = (u64*)(h1s + 2 * HBS);      // [4*HID] (b,b) pairs
    u64*   sb1  = sb0 + 4 * HID;
    u64*   swx  = sb1 + 4 * HID;
    float* fcws = (float*)(swx + 4 * HID);    // [0:50) w, [50] bias

    const int tid = threadIdx.x;

    // ---- stage weights; sigmoid-gate rows (g = 0,1,3) pre-scaled by 0.5 ----
    for (int idx = tid; idx < WMAT; idx += NTHREADS) {
        int row = idx / JP, col = idx - row * JP;
        int g = row / HID;
        float sc = (g == 2) ? 1.0f : 0.5f;
        float a = 0.f, b = 0.f, c = 0.f;
        if (col < HID) {
            a = sc * Whh0[row * HID + col];
            b = sc * Wih1[row * HID + col];
            c = sc * Whh1[row * HID + col];
        }
        w0s[idx]  = a;
        w1is[idx] = b;
        w1hs[idx] = c;
    }
    for (int idx = tid; idx < 5 * HBS; idx += NTHREADS)
        h0s[idx] = 0.0f;                      // zeros h0[3] and h1[2]
    if (tid < HID) {
        int u = tid;
        #pragma unroll
        for (int g = 0; g < 4; g++) {
            float sc = (g == 2) ? 1.0f : 0.5f;
            float b0v = sc * (bih0[g * HID + u] + bhh0[g * HID + u]);
            float b1v = sc * (bih1[g * HID + u] + bhh1[g * HID + u]);
            float wxv = sc * Wih0[g * HID + u];     // IN = 1
            sb0[g * HID + u] = pk2(b0v, b0v);
            sb1[g * HID + u] = pk2(b1v, b1v);
            swx[g * HID + u] = pk2(wxv, wxv);
        }
        fcws[u] = fcw_g[u];
    }
    if (tid == 0) fcws[HID] = fcb_g[0];

    // ---- group / lane mapping ----
    const bool isA = (tid < 400);
    const bool isB = (tid >= 416 && tid < 816);
    const int  gt  = isA ? tid : (isB ? (tid - 416) : 0);
    const int  bg  = gt & 7;
    const int  u   = gt >> 3;
    const int  bb  = bg * NBT;

    float cst[NBT] = {0.f, 0.f, 0.f, 0.f};   // c0 for A, c1 for B

    const float* xp = x + (size_t)(blockIdx.x * NBC + bb) * SEQT;
    float xv[NBT];
    if (isA) {
        #pragma unroll
        for (int nb = 0; nb < NBT; nb++) xv[nb] = xp[nb * SEQT + 0];
    }

    __syncthreads();

    for (int s = 0; s <= SEQT + 1; s++) {
        const int m_w  = s % 3;            // h0 write buffer   (h0(s))
        const int m_r1 = (s + 2) % 3;      // h0(s-1)
        const int m_r2 = (s + 1) % 3;      // h0(s-2)

        if (isA) {
            if (s < SEQT) {
                // ===== layer 0, t = s =====
                u64 accA[4], accB[4];
                {
                    u64 xxA = pk2(xv[0], xv[1]);
                    u64 xxB = pk2(xv[2], xv[3]);
                    #pragma unroll
                    for (int g = 0; g < 4; g++) {
                        u64 bv = sb0[g * HID + u];
                        u64 wx = swx[g * HID + u];
                        accA[g] = bv; fma2(accA[g], wx, xxA);
                        accB[g] = bv; fma2(accB[g], wx, xxB);
                    }
                }
                float xvn[NBT];
                {
                    const int tn = (s + 1 < SEQT) ? s + 1 : s;
                    #pragma unroll
                    for (int nb = 0; nb < NBT; nb++) xvn[nb] = xp[nb * SEQT + tn];
                }
                {
                    const float* w0r0 = w0s + (0 * HID + u) * JP;
                    const float* w0r1 = w0s + (1 * HID + u) * JP;
                    const float* w0r2 = w0s + (2 * HID + u) * JP;
                    const float* w0r3 = w0s + (3 * HID + u) * JP;
                    const float* hp   = h0s + m_r1 * HBS + bb;
                    for (int j4 = 0; j4 < JP; j4 += 4) {
                        float4 wi = *(const float4*)(w0r0 + j4);
                        float4 wf = *(const float4*)(w0r1 + j4);
                        float4 wg = *(const float4*)(w0r2 + j4);
                        float4 wo = *(const float4*)(w0r3 + j4);
                        ulonglong2 h0v = *(const ulonglong2*)(hp + (j4 + 0) * NBC);
                        ulonglong2 h1v = *(const ulonglong2*)(hp + (j4 + 1) * NBC);
                        ulonglong2 h2v = *(const ulonglong2*)(hp + (j4 + 2) * NBC);
                        ulonglong2 h3v = *(const ulonglong2*)(hp + (j4 + 3) * NBC);
                        fma2(accA[0], pk2(wi.x, wi.x), h0v.x); fma2(accB[0], pk2(wi.x, wi.x), h0v.y);
                        fma2(accA[1], pk2(wf.x, wf.x), h0v.x); fma2(accB[1], pk2(wf.x, wf.x), h0v.y);
                        fma2(accA[2], pk2(wg.x, wg.x), h0v.x); fma2(accB[2], pk2(wg.x, wg.x), h0v.y);
                        fma2(accA[3], pk2(wo.x, wo.x), h0v.x); fma2(accB[3], pk2(wo.x, wo.x), h0v.y);
                        fma2(accA[0], pk2(wi.y, wi.y), h1v.x); fma2(accB[0], pk2(wi.y, wi.y), h1v.y);
                        fma2(accA[1], pk2(wf.y, wf.y), h1v.x); fma2(accB[1], pk2(wf.y, wf.y), h1v.y);
                        fma2(accA[2], pk2(wg.y, wg.y), h1v.x); fma2(accB[2], pk2(wg.y, wg.y), h1v.y);
                        fma2(accA[3], pk2(wo.y, wo.y), h1v.x); fma2(accB[3], pk2(wo.y, wo.y), h1v.y);
                        fma2(accA[0], pk2(wi.z, wi.z), h2v.x); fma2(accB[0], pk2(wi.z, wi.z), h2v.y);
                        fma2(accA[1], pk2(wf.z, wf.z), h2v.x); fma2(accB[1], pk2(wf.z, wf.z), h2v.y);
                        fma2(accA[2], pk2(wg.z, wg.z), h2v.x); fma2(accB[2], pk2(wg.z, wg.z), h2v.y);
                        fma2(accA[3], pk2(wo.z, wo.z), h2v.x); fma2(accB[3], pk2(wo.z, wo.z), h2v.y);
                        fma2(accA[0], pk2(wi.w, wi.w), h3v.x); fma2(accB[0], pk2(wi.w, wi.w), h3v.y);
                        fma2(accA[1], pk2(wf.w, wf.w), h3v.x); fma2(accB[1], pk2(wf.w, wf.w), h3v.y);
                        fma2(accA[2], pk2(wg.w, wg.w), h3v.x); fma2(accB[2], pk2(wg.w, wg.w), h3v.y);
                        fma2(accA[3], pk2(wo.w, wo.w), h3v.x); fma2(accB[3], pk2(wo.w, wo.w), h3v.y);
                    }
                }
                {
                    float gi[4] = {lo2(accA[0]), hi2(accA[0]), lo2(accB[0]), hi2(accB[0])};
                    float gf[4] = {lo2(accA[1]), hi2(accA[1]), lo2(accB[1]), hi2(accB[1])};
                    float gz[4] = {lo2(accA[2]), hi2(accA[2]), lo2(accB[2]), hi2(accB[2])};
                    float go[4] = {lo2(accA[3]), hi2(accA[3]), lo2(accB[3]), hi2(accB[3])};
                    float hn[4];
                    #pragma unroll
                    for (int nb = 0; nb < NBT; nb++) {
                        float ig = sig_h(gi[nb]);       // accs pre-halved via weights
                        float fg = sig_h(gf[nb]);
                        float zg = tanha(gz[nb]);
                        float og = sig_h(go[nb]);
                        cst[nb] = fg * cst[nb] + ig * zg;
                        hn[nb] = og * tanha(cst[nb]);
                    }
                    *(float4*)(h0s + m_w * HBS + u * NBC + bb) =
                        make_float4(hn[0], hn[1], hn[2], hn[3]);
                }
                #pragma unroll
                for (int nb = 0; nb < NBT; nb++) xv[nb] = xvn[nb];
            }
            if (s <= SEQT) {
                // ===== partialA(t = s-1) = b1 + Wih1[:, 0:JA] @ h0(s-1) =====
                u64 accA[4], accB[4];
                #pragma unroll
                for (int g = 0; g < 4; g++) {
                    u64 bv = sb1[g * HID + u];
                    accA[g] = bv; accB[g] = bv;
                }
                {
                    const float* wr0 = w1is + (0 * HID + u) * JP;
                    const float* wr1 = w1is + (1 * HID + u) * JP;
                    const float* wr2 = w1is + (2 * HID + u) * JP;
                    const float* wr3 = w1is + (3 * HID + u) * JP;
                    const float* hp  = h0s + m_r1 * HBS + bb;
                    for (int j4 = 0; j4 < JA; j4 += 4) {
                        float4 wi = *(const float4*)(wr0 + j4);
                        float4 wf = *(const float4*)(wr1 + j4);
                        float4 wg = *(const float4*)(wr2 + j4);
                        float4 wo = *(const float4*)(wr3 + j4);
                        ulonglong2 h0v = *(const ulonglong2*)(hp + (j4 + 0) * NBC);
                        ulonglong2 h1v = *(const ulonglong2*)(hp + (j4 + 1) * NBC);
                        ulonglong2 h2v = *(const ulonglong2*)(hp + (j4 + 2) * NBC);
                        ulonglong2 h3v = *(const ulonglong2*)(hp + (j4 + 3) * NBC);
                        fma2(accA[0], pk2(wi.x, wi.x), h0v.x); fma2(accB[0], pk2(wi.x, wi.x), h0v.y);
                        fma2(accA[1], pk2(wf.x, wf.x), h0v.x); fma2(accB[1], pk2(wf.x, wf.x), h0v.y);
                        fma2(accA[2], pk2(wg.x, wg.x), h0v.x); fma2(accB[2], pk2(wg.x, wg.x), h0v.y);
                        fma2(accA[3], pk2(wo.x, wo.x), h0v.x); fma2(accB[3], pk2(wo.x, wo.x), h0v.y);
                        fma2(accA[0], pk2(wi.y, wi.y), h1v.x); fma2(accB[0], pk2(wi.y, wi.y), h1v.y);
                        fma2(accA[1], pk2(wf.y, wf.y), h1v.x); fma2(accB[1], pk2(wf.y, wf.y), h1v.y);
                        fma2(accA[2], pk2(wg.y, wg.y), h1v.x); fma2(accB[2], pk2(wg.y, wg.y), h1v.y);
                        fma2(accA[3], pk2(wo.y, wo.y), h1v.x); fma2(accB[3], pk2(wo.y, wo.y), h1v.y);
                        fma2(accA[0], pk2(wi.z, wi.z), h2v.x); fma2(accB[0], pk2(wi.z, wi.z), h2v.y);
                        fma2(accA[1], pk2(wf.z, wf.z), h2v.x); fma2(accB[1], pk2(wf.z, wf.z), h2v.y);
                        fma2(accA[2], pk2(wg.z, wg.z), h2v.x); fma2(accB[2], pk2(wg.z, wg.z), h2v.y);
                        fma2(accA[3], pk2(wo.z, wo.z), h2v.x); fma2(accB[3], pk2(wo.z, wo.z), h2v.y);
                        fma2(accA[0], pk2(wi.w, wi.w), h3v.x); fma2(accB[0], pk2(wi.w, wi.w), h3v.y);
                        fma2(accA[1], pk2(wf.w, wf.w), h3v.x); fma2(accB[1], pk2(wf.w, wf.w), h3v.y);
                        fma2(accA[2], pk2(wg.w, wg.w), h3v.x); fma2(accB[2], pk2(wg.w, wg.w), h3v.y);
                        fma2(accA[3], pk2(wo.w, wo.w), h3v.x); fma2(accB[3], pk2(wo.w, wo.w), h3v.y);
                    }
                }
                u64* pzw = pz + (s & 1) * PZ_U64 + (u * 8 + bg) * 8;
                *(ulonglong2*)(pzw + 0) = make_ulonglong2(accA[0], accA[1]);
                *(ulonglong2*)(pzw + 2) = make_ulonglong2(accA[2], accA[3]);
                *(ulonglong2*)(pzw + 4) = make_ulonglong2(accB[0], accB[1]);
                *(ulonglong2*)(pzw + 6) = make_ulonglong2(accB[2], accB[3]);
            }
        } else if (isB) {
            if (s >= 2) {
                // ===== layer 1, t = s-2 =====
                u64 accA[4], accB[4];
                {
                    const u64* pzr = pz + ((s + 1) & 1) * PZ_U64 + (u * 8 + bg) * 8;
                    ulonglong2 p0 = *(const ulonglong2*)(pzr + 0);
                    ulonglong2 p1 = *(const ulonglong2*)(pzr + 2);
                    ulonglong2 p2 = *(const ulonglong2*)(pzr + 4);
                    ulonglong2 p3 = *(const ulonglong2*)(pzr + 6);
                    accA[0] = p0.x; accA[1] = p0.y; accA[2] = p1.x; accA[3] = p1.y;
                    accB[0] = p2.x; accB[1] = p2.y; accB[2] = p3.x; accB[3] = p3.y;
                }
                {
                    // Whh1 @ h1(t-1), full JP
                    const float* wr0 = w1hs + (0 * HID + u) * JP;
                    const float* wr1 = w1hs + (1 * HID + u) * JP;
                    const float* wr2 = w1hs + (2 * HID + u) * JP;
                    const float* wr3 = w1hs + (3 * HID + u) * JP;
                    const float* hp  = h1s + ((s + 1) & 1) * HBS + bb;   // h1(t-1)
                    for (int j4 = 0; j4 < JP; j4 += 4) {
                        float4 wi = *(const float4*)(wr0 + j4);
                        float4 wf = *(const float4*)(wr1 + j4);
                        float4 wg = *(const float4*)(wr2 + j4);
                        float4 wo = *(const float4*)(wr3 + j4);
                        ulonglong2 h0v = *(const ulonglong2*)(hp + (j4 + 0) * NBC);
                        ulonglong2 h1v = *(const ulonglong2*)(hp + (j4 + 1) * NBC);
                        ulonglong2 h2v = *(const ulonglong2*)(hp + (j4 + 2) * NBC);
                        ulonglong2 h3v = *(const ulonglong2*)(hp + (j4 + 3) * NBC);
                        fma2(accA[0], pk2(wi.x, wi.x), h0v.x); fma2(accB[0], pk2(wi.x, wi.x), h0v.y);
                        fma2(accA[1], pk2(wf.x, wf.x), h0v.x); fma2(accB[1], pk2(wf.x, wf.x), h0v.y);
                        fma2(accA[2], pk2(wg.x, wg.x), h0v.x); fma2(accB[2], pk2(wg.x, wg.x), h0v.y);
                        fma2(accA[3], pk2(wo.x, wo.x), h0v.x); fma2(accB[3], pk2(wo.x, wo.x), h0v.y);
                        fma2(accA[0], pk2(wi.y, wi.y), h1v.x); fma2(accB[0], pk2(wi.y, wi.y), h1v.y);
                        fma2(accA[1], pk2(wf.y, wf.y), h1v.x); fma2(accB[1], pk2(wf.y, wf.y), h1v.y);
                        fma2(accA[2], pk2(wg.y, wg.y), h1v.x); fma2(accB[2], pk2(wg.y, wg.y), h1v.y);
                        fma2(accA[3], pk2(wo.y, wo.y), h1v.x); fma2(accB[3], pk2(wo.y, wo.y), h1v.y);
                        fma2(accA[0], pk2(wi.z, wi.z), h2v.x); fma2(accB[0], pk2(wi.z, wi.z), h2v.y);
                        fma2(accA[1], pk2(wf.z, wf.z), h2v.x); fma2(accB[1], pk2(wf.z, wf.z), h2v.y);
                        fma2(accA[2], pk2(wg.z, wg.z), h2v.x); fma2(accB[2], pk2(wg.z, wg.z), h2v.y);
                        fma2(accA[3], pk2(wo.z, wo.z), h2v.x); fma2(accB[3], pk2(wo.z, wo.z), h2v.y);
                        fma2(accA[0], pk2(wi.w, wi.w), h3v.x); fma2(accB[0], pk2(wi.w, wi.w), h3v.y);
                        fma2(accA[1], pk2(wf.w, wf.w), h3v.x); fma2(accB[1], pk2(wf.w, wf.w), h3v.y);
                        fma2(accA[2], pk2(wg.w, wg.w), h3v.x); fma2(accB[2], pk2(wg.w, wg.w), h3v.y);
                        fma2(accA[3], pk2(wo.w, wo.w), h3v.x); fma2(accB[3], pk2(wo.w, wo.w), h3v.y);
                    }
                }
                {
                    // Wih1[:, JA:] @ h0(t)
                    const float* wr0 = w1is + (0 * HID + u) * JP;
                    const float* wr1 = w1is + (1 * HID + u) * JP;
                    const float* wr2 = w1is + (2 * HID + u) * JP;
                    const float* wr3 = w1is + (3 * HID + u) * JP;
                    const float* hp  = h0s + m_r2 * HBS + bb;            // h0(t = s-2)
                    for (int j4 = JA; j4 < JP; j4 += 4) {
                        float4 wi = *(const float4*)(wr0 + j4);
                        float4 wf = *(const float4*)(wr1 + j4);
                        float4 wg = *(const float4*)(wr2 + j4);
                        float4 wo = *(const float4*)(wr3 + j4);
                        ulonglong2 h0v = *(const ulonglong2*)(hp + (j4 + 0) * NBC);
                        ulonglong2 h1v = *(const ulonglong2*)(hp + (j4 + 1) * NBC);
                        ulonglong2 h2v = *(const ulonglong2*)(hp + (j4 + 2) * NBC);
                        ulonglong2 h3v = *(const ulonglong2*)(hp + (j4 + 3) * NBC);
                        fma2(accA[0], pk2(wi.x, wi.x), h0v.x); fma2(accB[0], pk2(wi.x, wi.x), h0v.y);
                        fma2(accA[1], pk2(wf.x, wf.x), h0v.x); fma2(accB[1], pk2(wf.x, wf.x), h0v.y);
                        fma2(accA[2], pk2(wg.x, wg.x), h0v.x); fma2(accB[2], pk2(wg.x, wg.x), h0v.y);
                        fma2(accA[3], pk2(wo.x, wo.x), h0v.x); fma2(accB[3], pk2(wo.x, wo.x), h0v.y);
                        fma2(accA[0], pk2(wi.y, wi.y), h1v.x); fma2(accB[0], pk2(wi.y, wi.y), h1v.y);
                        fma2(accA[1], pk2(wf.y, wf.y), h1v.x); fma2(accB[1], pk2(wf.y, wf.y), h1v.y);
                        fma2(accA[2], pk2(wg.y, wg.y), h1v.x); fma2(accB[2], pk2(wg.y, wg.y), h1v.y);
                        fma2(accA[3], pk2(wo.y, wo.y), h1v.x); fma2(accB[3], pk2(wo.y, wo.y), h1v.y);
                        fma2(accA[0], pk2(wi.z, wi.z), h2v.x); fma2(accB[0], pk2(wi.z, wi.z), h2v.y);
                        fma2(accA[1], pk2(wf.z, wf.z), h2v.x); fma2(accB[1], pk2(wf.z, wf.z), h2v.y);
                        fma2(accA[2], pk2(wg.z, wg.z), h2v.x); fma2(accB[2], pk2(wg.z, wg.z), h2v.y);
                        fma2(accA[3], pk2(wo.z, wo.z), h2v.x); fma2(accB[3], pk2(wo.z, wo.z), h2v.y);
                        fma2(accA[0], pk2(wi.w, wi.w), h3v.x); fma2(accB[0], pk2(wi.w, wi.w), h3v.y);
                        fma2(accA[1], pk2(wf.w, wf.w), h3v.x); fma2(accB[1], pk2(wf.w, wf.w), h3v.y);
                        fma2(accA[2], pk2(wg.w, wg.w), h3v.x); fma2(accB[2], pk2(wg.w, wg.w), h3v.y);
                        fma2(accA[3], pk2(wo.w, wo.w), h3v.x); fma2(accB[3], pk2(wo.w, wo.w), h3v.y);
                    }
                }
                {
                    float gi[4] = {lo2(accA[0]), hi2(accA[0]), lo2(accB[0]), hi2(accB[0])};
                    float gf[4] = {lo2(accA[1]), hi2(accA[1]), lo2(accB[1]), hi2(accB[1])};
                    float gz[4] = {lo2(accA[2]), hi2(accA[2]), lo2(accB[2]), hi2(accB[2])};
                    float go[4] = {lo2(accA[3]), hi2(accA[3]), lo2(accB[3]), hi2(accB[3])};
                    float hn[4];
                    #pragma unroll
                    for (int nb = 0; nb < NBT; nb++) {
                        float ig = sig_h(gi[nb]);
                        float fg = sig_h(gf[nb]);
                        float zg = tanha(gz[nb]);
                        float og = sig_h(go[nb]);
                        cst[nb] = fg * cst[nb] + ig * zg;
                        hn[nb] = og * tanha(cst[nb]);
                    }
                    *(float4*)(h1s + (s & 1) * HBS + u * NBC + bb) =
                        make_float4(hn[0], hn[1], hn[2], hn[3]);
                }
            }
        }
        __syncthreads();
    }

    // ===== final projection: out[b] = h1(T-1)[:, b] . fcw + fcb =====
    // h1(511) written at s=513 into parity (513&1)=1 -> buffer 1
    if (tid < NBC) {
        float acc = fcws[HID];
        const float* hf = h1s + HBS;
        #pragma unroll 10
        for (int uu = 0; uu < HID; uu++)
            acc += hf[uu * NBC + tid] * fcws[uu];
        out[blockIdx.x * NBC + tid] = acc;
    }
}

extern "C" void kernel_launch(void* const* d_in, const int* in_sizes, int n_in,
                              void* d_out, int out_size)
{
    const float* x    = (const float*)d_in[0];
    const float* Wih0 = (const float*)d_in[1];
    const float* Whh0 = (const float*)d_in[2];
    const float* bih0 = (const float*)d_in[3];
    const float* bhh0 = (const float*)d_in[4];
    const float* Wih1 = (const float*)d_in[5];
    const float* Whh1 = (const float*)d_in[6];
    const float* bih1 = (const float*)d_in[7];
    const float* bhh1 = (const float*)d_in[8];
    const float* fcw  = (const float*)d_in[9];
    const float* fcb  = (const float*)d_in[10];
    float* out = (float*)d_out;

    cudaFuncSetAttribute(lstm_fused_kernel,
                         cudaFuncAttributeMaxDynamicSharedMemorySize, SMEM_BYTES);
    lstm_fused_kernel<<<NCTAS, NTHREADS, SMEM_BYTES>>>(
        x, Wih0, Whh0, bih0, bhh0, Wih1, Whh1, bih1, bhh1, fcw, fcb, out);
}

// round 14
// speedup vs baseline: 1.6715x; 1.0835x over previous
#include <cuda_runtime.h>

// Problem constants
#define BATCH    4096
#define SEQT     512
#define HID      50
#define NBC      32               // batch per CTA
#define NBT      8                // batch per thread
#define NTHREADS 448              // A: warps 0-6 (gt<200), B: warps 7-13 (gt<200)
#define NCTAS    128
#define JP       52               // padded j extent (cols 50,51 zero)
#define JA       24               // A computes Wih1 partial j<JA; B does j>=JA
#define HBS      (JP * NBC)       // floats per h buffer = 1664
#define WMAT     (4 * HID * JP)   // floats per weight matrix = 10400
#define PZ_STRIDE 18              // u64 per thread slot (bank-conflict-free)
#define PZ_U64   (200 * PZ_STRIDE)

typedef unsigned long long u64;

__device__ __forceinline__ void fma2(u64 &acc, u64 a, u64 b) {
    asm("fma.rn.f32x2 %0, %1, %2, %0;" : "+l"(acc) : "l"(a), "l"(b));
}
__device__ __forceinline__ u64 pk2(float a, float b) {
    u64 r;
    unsigned ia = __float_as_uint(a), ib = __float_as_uint(b);
    asm("mov.b64 %0, {%1, %2};" : "=l"(r) : "r"(ia), "r"(ib));
    return r;
}
__device__ __forceinline__ float lo2(u64 v) { return __uint_as_float((unsigned)v); }
__device__ __forceinline__ float hi2(u64 v) { return __uint_as_float((unsigned)(v >> 32)); }

// HW tanh (MUFU)
__device__ __forceinline__ float tanha(float z) {
    float r;
    asm("tanh.approx.f32 %0, %1;" : "=f"(r) : "f"(z));
    return r;
}
// sigmoid with pre-halved argument: sig(2z') = 0.5 + 0.5*tanh(z')
__device__ __forceinline__ float sig_h(float zh) {
    return fmaf(0.5f, tanha(zh), 0.5f);
}

// one j-column of the matmul for 8 batches (4 f32x2 pairs per gate)
__device__ __forceinline__ void gate8(u64* aI, u64* aF, u64* aG, u64* aO,
                                      float wi, float wf, float wg, float wo,
                                      ulonglong2 hA, ulonglong2 hB) {
    u64 pwi = pk2(wi, wi), pwf = pk2(wf, wf), pwg = pk2(wg, wg), pwo = pk2(wo, wo);
    fma2(aI[0], pwi, hA.x); fma2(aI[1], pwi, hA.y); fma2(aI[2], pwi, hB.x); fma2(aI[3], pwi, hB.y);
    fma2(aF[0], pwf, hA.x); fma2(aF[1], pwf, hA.y); fma2(aF[2], pwf, hB.x); fma2(aF[3], pwf, hB.y);
    fma2(aG[0], pwg, hA.x); fma2(aG[1], pwg, hA.y); fma2(aG[2], pwg, hB.x); fma2(aG[3], pwg, hB.y);
    fma2(aO[0], pwo, hA.x); fma2(aO[1], pwo, hA.y); fma2(aO[2], pwo, hB.x); fma2(aO[3], pwo, hB.y);
}

// SMEM: pz[2][PZ_U64] | w0s w1is w1hs (floats) | h0s[3][HBS] h1s[2][HBS] |
//       sb0 sb1 swx (u64[4*HID]) | fcw[52]
#define SMEM_BYTES (2*PZ_U64*8 + 3*WMAT*4 + 5*HBS*4 + 3*4*HID*8 + 52*4)

__global__ __launch_bounds__(NTHREADS, 1)
void lstm_fused_kernel(const float* __restrict__ x,
                       const float* __restrict__ Wih0, const float* __restrict__ Whh0,
                       const float* __restrict__ bih0, const float* __restrict__ bhh0,
                       const float* __restrict__ Wih1, const float* __restrict__ Whh1,
                       const float* __restrict__ bih1, const float* __restrict__ bhh1,
                       const float* __restrict__ fcw_g, const float* __restrict__ fcb_g,
                       float* __restrict__ out)
{
    extern __shared__ u64 smu[];
    u64*   pz   = smu;                        // [2][PZ_U64]
    float* w0s  = (float*)(pz + 2 * PZ_U64);  // layer0 Whh   [4H][JP]
    float* w1is = w0s  + WMAT;                // layer1 Wih
    float* w1hs = w1is + WMAT;                // layer1 Whh
    float* h0s  = w1hs + WMAT;                // [3][JP][NBC]
    float* h1s  = h0s  + 3 * HBS;             // [2][JP][NBC]
    u64*   sb0  = (u64*)(h1s + 2 * HBS);      // [4*HID] (b,b) pairs
    u64*   sb1  = sb0 + 4 * HID;
    u64*   swx  = sb1 + 4 * HID;
    float* fcws = (float*)(swx + 4 * HID);    // [0:50) w, [50] bias

    const int tid = threadIdx.x;

    // ---- stage weights; sigmoid-gate rows (g = 0,1,3) pre-scaled by 0.5 ----
    for (int idx = tid; idx < WMAT; idx += NTHREADS) {
        int row = idx / JP, col = idx - row * JP;
        int g = row / HID;
        float sc = (g == 2) ? 1.0f : 0.5f;
        float a = 0.f, b = 0.f, c = 0.f;
        if (col < HID) {
            a = sc * Whh0[row * HID + col];
            b = sc * Wih1[row * HID + col];
            c = sc * Whh1[row * HID + col];
        }
        w0s[idx]  = a;
        w1is[idx] = b;
        w1hs[idx] = c;
    }
    for (int idx = tid; idx < 5 * HBS; idx += NTHREADS)
        h0s[idx] = 0.0f;                      // zeros h0[3] and h1[2]
    if (tid < HID) {
        int u = tid;
        #pragma unroll
        for (int g = 0; g < 4; g++) {
            float sc = (g == 2) ? 1.0f : 0.5f;
            float b0v = sc * (bih0[g * HID + u] + bhh0[g * HID + u]);
            float b1v = sc * (bih1[g * HID + u] + bhh1[g * HID + u]);
            float wxv = sc * Wih0[g * HID + u];     // IN = 1
            sb0[g * HID + u] = pk2(b0v, b0v);
            sb1[g * HID + u] = pk2(b1v, b1v);
            swx[g * HID + u] = pk2(wxv, wxv);
        }
        fcws[u] = fcw_g[u];
    }
    if (tid == 0) fcws[HID] = fcb_g[0];

    // ---- group / lane mapping (warp-aligned groups) ----
    const bool isA = (tid < 200);                 // warps 0-6 (lanes 200-223 idle)
    const bool isB = (tid >= 224 && tid < 424);   // warps 7-13 (lanes 424-447 idle)
    const int  gt  = isA ? tid : (isB ? (tid - 224) : 0);
    const int  bg  = gt & 3;          // batch group (fast in warp)
    const int  u   = gt >> 2;         // hidden unit 0..49
    const int  bb  = bg * NBT;        // local batch base (floats)

    float cst[NBT] = {0.f,0.f,0.f,0.f,0.f,0.f,0.f,0.f};   // c0 for A, c1 for B

    const float* xp = x + (size_t)(blockIdx.x * NBC + bb) * SEQT;
    float xv[NBT];
    if (isA) {
        #pragma unroll
        for (int nb = 0; nb < NBT; nb++) xv[nb] = xp[nb * SEQT + 0];
    }

    __syncthreads();

    for (int s = 0; s <= SEQT + 1; s++) {
        const int m_w  = s % 3;            // h0 write buffer   (h0(s))
        const int m_r1 = (s + 2) % 3;      // h0(s-1)
        const int m_r2 = (s + 1) % 3;      // h0(s-2)

        if (isA) {
            u64 aI[4], aF[4], aG[4], aO[4];
            if (s < SEQT) {
                // ===== layer 0, t = s =====
                {
                    u64 xx[4] = {pk2(xv[0], xv[1]), pk2(xv[2], xv[3]),
                                 pk2(xv[4], xv[5]), pk2(xv[6], xv[7])};
                    u64 bI = sb0[0*HID+u], bF = sb0[1*HID+u], bG = sb0[2*HID+u], bO = sb0[3*HID+u];
                    u64 wI = swx[0*HID+u], wF = swx[1*HID+u], wG = swx[2*HID+u], wO = swx[3*HID+u];
                    #pragma unroll
                    for (int p = 0; p < 4; p++) {
                        aI[p] = bI; fma2(aI[p], wI, xx[p]);
                        aF[p] = bF; fma2(aF[p], wF, xx[p]);
                        aG[p] = bG; fma2(aG[p], wG, xx[p]);
                        aO[p] = bO; fma2(aO[p], wO, xx[p]);
                    }
                }
                float xvn[NBT];
                {
                    const int tn = (s + 1 < SEQT) ? s + 1 : s;
                    #pragma unroll
                    for (int nb = 0; nb < NBT; nb++) xvn[nb] = xp[nb * SEQT + tn];
                }
                {
                    const float* w0r0 = w0s + (0 * HID + u) * JP;
                    const float* w0r1 = w0s + (1 * HID + u) * JP;
                    const float* w0r2 = w0s + (2 * HID + u) * JP;
                    const float* w0r3 = w0s + (3 * HID + u) * JP;
                    const float* hp   = h0s + m_r1 * HBS + bb;
                    for (int j4 = 0; j4 < JP; j4 += 4) {
                        float4 wi = *(const float4*)(w0r0 + j4);
                        float4 wf = *(const float4*)(w0r1 + j4);
                        float4 wg = *(const float4*)(w0r2 + j4);
                        float4 wo = *(const float4*)(w0r3 + j4);
                        const float* hj = hp + j4 * NBC;
                        ulonglong2 hA, hB;
                        hA = *(const ulonglong2*)(hj);           hB = *(const ulonglong2*)(hj + 4);
                        gate8(aI, aF, aG, aO, wi.x, wf.x, wg.x, wo.x, hA, hB);
                        hA = *(const ulonglong2*)(hj + NBC);     hB = *(const ulonglong2*)(hj + NBC + 4);
                        gate8(aI, aF, aG, aO, wi.y, wf.y, wg.y, wo.y, hA, hB);
                        hA = *(const ulonglong2*)(hj + 2*NBC);   hB = *(const ulonglong2*)(hj + 2*NBC + 4);
                        gate8(aI, aF, aG, aO, wi.z, wf.z, wg.z, wo.z, hA, hB);
                        hA = *(const ulonglong2*)(hj + 3*NBC);   hB = *(const ulonglong2*)(hj + 3*NBC + 4);
                        gate8(aI, aF, aG, aO, wi.w, wf.w, wg.w, wo.w, hA, hB);
                    }
                }
                {
                    float gi[8] = {lo2(aI[0]),hi2(aI[0]),lo2(aI[1]),hi2(aI[1]),lo2(aI[2]),hi2(aI[2]),lo2(aI[3]),hi2(aI[3])};
                    float gf[8] = {lo2(aF[0]),hi2(aF[0]),lo2(aF[1]),hi2(aF[1]),lo2(aF[2]),hi2(aF[2]),lo2(aF[3]),hi2(aF[3])};
                    float gz[8] = {lo2(aG[0]),hi2(aG[0]),lo2(aG[1]),hi2(aG[1]),lo2(aG[2]),hi2(aG[2]),lo2(aG[3]),hi2(aG[3])};
                    float go[8] = {lo2(aO[0]),hi2(aO[0]),lo2(aO[1]),hi2(aO[1]),lo2(aO[2]),hi2(aO[2]),lo2(aO[3]),hi2(aO[3])};
                    float hn[8];
                    #pragma unroll
                    for (int nb = 0; nb < NBT; nb++) {
                        float ig = sig_h(gi[nb]);
                        float fg = sig_h(gf[nb]);
                        float zg = tanha(gz[nb]);
                        float og = sig_h(go[nb]);
                        cst[nb] = fg * cst[nb] + ig * zg;
                        hn[nb] = og * tanha(cst[nb]);
                    }
                    float* hw = h0s + m_w * HBS + u * NBC + bb;
                    *(float4*)(hw)     = make_float4(hn[0], hn[1], hn[2], hn[3]);
                    *(float4*)(hw + 4) = make_float4(hn[4], hn[5], hn[6], hn[7]);
                }
                #pragma unroll
                for (int nb = 0; nb < NBT; nb++) xv[nb] = xvn[nb];
            }
            if (s <= SEQT) {
                // ===== partialA(t = s-1) = b1 + Wih1[:, 0:JA] @ h0(s-1) =====
                #pragma unroll
                for (int p = 0; p < 4; p++) {
                    aI[p] = sb1[0*HID+u]; aF[p] = sb1[1*HID+u];
                    aG[p] = sb1[2*HID+u]; aO[p] = sb1[3*HID+u];
                }
                {
                    const float* wr0 = w1is + (0 * HID + u) * JP;
                    const float* wr1 = w1is + (1 * HID + u) * JP;
                    const float* wr2 = w1is + (2 * HID + u) * JP;
                    const float* wr3 = w1is + (3 * HID + u) * JP;
                    const float* hp  = h0s + m_r1 * HBS + bb;
                    for (int j4 = 0; j4 < JA; j4 += 4) {
                        float4 wi = *(const float4*)(wr0 + j4);
                        float4 wf = *(const float4*)(wr1 + j4);
                        float4 wg = *(const float4*)(wr2 + j4);
                        float4 wo = *(const float4*)(wr3 + j4);
                        const float* hj = hp + j4 * NBC;
                        ulonglong2 hA, hB;
                        hA = *(const ulonglong2*)(hj);           hB = *(const ulonglong2*)(hj + 4);
                        gate8(aI, aF, aG, aO, wi.x, wf.x, wg.x, wo.x, hA, hB);
                        hA = *(const ulonglong2*)(hj + NBC);     hB = *(const ulonglong2*)(hj + NBC + 4);
                        gate8(aI, aF, aG, aO, wi.y, wf.y, wg.y, wo.y, hA, hB);
                        hA = *(const ulonglong2*)(hj + 2*NBC);   hB = *(const ulonglong2*)(hj + 2*NBC + 4);
                        gate8(aI, aF, aG, aO, wi.z, wf.z, wg.z, wo.z, hA, hB);
                        hA = *(const ulonglong2*)(hj + 3*NBC);   hB = *(const ulonglong2*)(hj + 3*NBC + 4);
                        gate8(aI, aF, aG, aO, wi.w, wf.w, wg.w, wo.w, hA, hB);
                    }
                }
                u64* pzw = pz + (s & 1) * PZ_U64 + gt * PZ_STRIDE;
                *(ulonglong2*)(pzw + 0)  = make_ulonglong2(aI[0], aI[1]);
                *(ulonglong2*)(pzw + 2)  = make_ulonglong2(aI[2], aI[3]);
                *(ulonglong2*)(pzw + 4)  = make_ulonglong2(aF[0], aF[1]);
                *(ulonglong2*)(pzw + 6)  = make_ulonglong2(aF[2], aF[3]);
                *(ulonglong2*)(pzw + 8)  = make_ulonglong2(aG[0], aG[1]);
                *(ulonglong2*)(pzw + 10) = make_ulonglong2(aG[2], aG[3]);
                *(ulonglong2*)(pzw + 12) = make_ulonglong2(aO[0], aO[1]);
                *(ulonglong2*)(pzw + 14) = make_ulonglong2(aO[2], aO[3]);
            }
        } else if (isB) {
            if (s >= 2) {
                // ===== layer 1, t = s-2 =====
                u64 aI[4], aF[4], aG[4], aO[4];
                {
                    const u64* pzr = pz + ((s + 1) & 1) * PZ_U64 + gt * PZ_STRIDE;
                    ulonglong2 q0 = *(const ulonglong2*)(pzr + 0);
                    ulonglong2 q1 = *(const ulonglong2*)(pzr + 2);
                    ulonglong2 q2 = *(const ulonglong2*)(pzr + 4);
                    ulonglong2 q3 = *(const ulonglong2*)(pzr + 6);
                    ulonglong2 q4 = *(const ulonglong2*)(pzr + 8);
                    ulonglong2 q5 = *(const ulonglong2*)(pzr + 10);
                    ulonglong2 q6 = *(const ulonglong2*)(pzr + 12);
                    ulonglong2 q7 = *(const ulonglong2*)(pzr + 14);
                    aI[0] = q0.x; aI[1] = q0.y; aI[2] = q1.x; aI[3] = q1.y;
                    aF[0] = q2.x; aF[1] = q2.y; aF[2] = q3.x; aF[3] = q3.y;
                    aG[0] = q4.x; aG[1] = q4.y; aG[2] = q5.x; aG[3] = q5.y;
                    aO[0] = q6.x; aO[1] = q6.y; aO[2] = q7.x; aO[3] = q7.y;
                }
                {
                    // Whh1 @ h1(t-1), full JP
                    const float* wr0 = w1hs + (0 * HID + u) * JP;
                    const float* wr1 = w1hs + (1 * HID + u) * JP;
                    const float* wr2 = w1hs + (2 * HID + u) * JP;
                    const float* wr3 = w1hs + (3 * HID + u) * JP;
                    const float* hp  = h1s + ((s + 1) & 1) * HBS + bb;   // h1(t-1)
                    for (int j4 = 0; j4 < JP; j4 += 4) {
                        float4 wi = *(const float4*)(wr0 + j4);
                        float4 wf = *(const float4*)(wr1 + j4);
                        float4 wg = *(const float4*)(wr2 + j4);
                        float4 wo = *(const float4*)(wr3 + j4);
                        const float* hj = hp + j4 * NBC;
                        ulonglong2 hA, hB;
                        hA = *(const ulonglong2*)(hj);           hB = *(const ulonglong2*)(hj + 4);
                        gate8(aI, aF, aG, aO, wi.x, wf.x, wg.x, wo.x, hA, hB);
                        hA = *(const ulonglong2*)(hj + NBC);     hB = *(const ulonglong2*)(hj + NBC + 4);
                        gate8(aI, aF, aG, aO, wi.y, wf.y, wg.y, wo.y, hA, hB);
                        hA = *(const ulonglong2*)(hj + 2*NBC);   hB = *(const ulonglong2*)(hj + 2*NBC + 4);
                        gate8(aI, aF, aG, aO, wi.z, wf.z, wg.z, wo.z, hA, hB);
                        hA = *(const ulonglong2*)(hj + 3*NBC);   hB = *(const ulonglong2*)(hj + 3*NBC + 4);
                        gate8(aI, aF, aG, aO, wi.w, wf.w, wg.w, wo.w, hA, hB);
                    }
                }
                {
                    // Wih1[:, JA:] @ h0(t)
                    const float* wr0 = w1is + (0 * HID + u) * JP;
                    const float* wr1 = w1is + (1 * HID + u) * JP;
                    const float* wr2 = w1is + (2 * HID + u) * JP;
                    const float* wr3 = w1is + (3 * HID + u) * JP;
                    const float* hp  = h0s + m_r2 * HBS + bb;            // h0(t = s-2)
                    for (int j4 = JA; j4 < JP; j4 += 4) {
                        float4 wi = *(const float4*)(wr0 + j4);
                        float4 wf = *(const float4*)(wr1 + j4);
                        float4 wg = *(const float4*)(wr2 + j4);
                        float4 wo = *(const float4*)(wr3 + j4);
                        const float* hj = hp + j4 * NBC;
                        ulonglong2 hA, hB;
                        hA = *(const ulonglong2*)(hj);           hB = *(const ulonglong2*)(hj + 4);
                        gate8(aI, aF, aG, aO, wi.x, wf.x, wg.x, wo.x, hA, hB);
                        hA = *(const ulonglong2*)(hj + NBC);     hB = *(const ulonglong2*)(hj + NBC + 4);
                        gate8(aI, aF, aG, aO, wi.y, wf.y, wg.y, wo.y, hA, hB);
                        hA = *(const ulonglong2*)(hj + 2*NBC);   hB = *(const ulonglong2*)(hj + 2*NBC + 4);
                        gate8(aI, aF, aG, aO, wi.z, wf.z, wg.z, wo.z, hA, hB);
                        hA = *(const ulonglong2*)(hj + 3*NBC);   hB = *(const ulonglong2*)(hj + 3*NBC + 4);
                        gate8(aI, aF, aG, aO, wi.w, wf.w, wg.w, wo.w, hA, hB);
                    }
                }
                {
                    float gi[8] = {lo2(aI[0]),hi2(aI[0]),lo2(aI[1]),hi2(aI[1]),lo2(aI[2]),hi2(aI[2]),lo2(aI[3]),hi2(aI[3])};
                    float gf[8] = {lo2(aF[0]),hi2(aF[0]),lo2(aF[1]),hi2(aF[1]),lo2(aF[2]),hi2(aF[2]),lo2(aF[3]),hi2(aF[3])};
                    float gz[8] = {lo2(aG[0]),hi2(aG[0]),lo2(aG[1]),hi2(aG[1]),lo2(aG[2]),hi2(aG[2]),lo2(aG[3]),hi2(aG[3])};
                    float go[8] = {lo2(aO[0]),hi2(aO[0]),lo2(aO[1]),hi2(aO[1]),lo2(aO[2]),hi2(aO[2]),lo2(aO[3]),hi2(aO[3])};
                    float hn[8];
                    #pragma unroll
                    for (int nb = 0; nb < NBT; nb++) {
                        float ig = sig_h(gi[nb]);
                        float fg = sig_h(gf[nb]);
                        float zg = tanha(gz[nb]);
                        float og = sig_h(go[nb]);
                        cst[nb] = fg * cst[nb] + ig * zg;
                        hn[nb] = og * tanha(cst[nb]);
                    }
                    float* hw = h1s + (s & 1) * HBS + u * NBC + bb;
                    *(float4*)(hw)     = make_float4(hn[0], hn[1], hn[2], hn[3]);
                    *(float4*)(hw + 4) = make_float4(hn[4], hn[5], hn[6], hn[7]);
                }
            }
        }
        __syncthreads();
    }

    // ===== final projection: out[b] = h1(T-1)[:, b] . fcw + fcb =====
    // h1(511) written at s=513 into parity 1 -> buffer 1
    if (tid < NBC) {
        float acc = fcws[HID];
        const float* hf = h1s + HBS;
        #pragma unroll 10
        for (int uu = 0; uu < HID; uu++)
            acc += hf[uu * NBC + tid] * fcws[uu];
        out[blockIdx.x * NBC + tid] = acc;
    }
}

extern "C" void kernel_launch(void* const* d_in, const int* in_sizes, int n_in,
                              void* d_out, int out_size)
{
    const float* x    = (const float*)d_in[0];
    const float* Wih0 = (const float*)d_in[1];
    const float* Whh0 = (const float*)d_in[2];
    const float* bih0 = (const float*)d_in[3];
    const float* bhh0 = (const float*)d_in[4];
    const float* Wih1 = (const float*)d_in[5];
    const float* Whh1 = (const float*)d_in[6];
    const float* bih1 = (const float*)d_in[7];
    const float* bhh1 = (const float*)d_in[8];
    const float* fcw  = (const float*)d_in[9];
    const float* fcb  = (const float*)d_in[10];
    float* out = (float*)d_out;

    cudaFuncSetAttribute(lstm_fused_kernel,
                         cudaFuncAttributeMaxDynamicSharedMemorySize, SMEM_BYTES);
    lstm_fused_kernel<<<NCTAS, NTHREADS, SMEM_BYTES>>>(
        x, Wih0, Whh0, bih0, bhh0, Wih1, Whh1, bih1, bhh1, fcw, fcb, out);
}